// round 10
// baseline (speedup 1.0000x reference)
#include <cuda_runtime.h>
#include <cstdint>

// MetapathGATConv fused kernel, R5: barrier-free streamed-W tf32 GEMMs
// (Wl+Wr both LDG.128 from L2, 1-slice register prefetch), i-blocked logits.

#define RREL   8
#define EMBED  256
#define NB     8
#define ROWS   64
#define PITCH  260
#define NTHREADS 512
#define KSTEPS 32
#define SLICE_F4 512
#define WMAT_F4 (KSTEPS * SLICE_F4)

__device__ float4 g_Wf[4 * WMAT_F4];   // Wl0 | Wr0 | Wl1 | Wr1, fragment-major tf32

__device__ __forceinline__ float tf32r(float x) {
    uint32_t u;
    asm("cvt.rna.tf32.f32 %0, %1;" : "=r"(u) : "f"(x));
    return __uint_as_float(u);
}
__device__ __forceinline__ float leaky(float v) { return v > 0.f ? v : 0.2f * v; }

__device__ __forceinline__ void mma_tf32(float* c, const uint32_t* a, const uint32_t* b) {
    asm volatile(
        "mma.sync.aligned.m16n8k8.row.col.f32.tf32.tf32.f32 "
        "{%0,%1,%2,%3}, {%4,%5,%6,%7}, {%8,%9}, {%0,%1,%2,%3};"
        : "+f"(c[0]), "+f"(c[1]), "+f"(c[2]), "+f"(c[3])
        : "r"(a[0]), "r"(a[1]), "r"(a[2]), "r"(a[3]), "r"(b[0]), "r"(b[1]));
}

// W repack: Wf[mat][s][grp][lane] fragment-major tf32.
__global__ void repack_W(const float* __restrict__ Wl0, const float* __restrict__ Wr0,
                         const float* __restrict__ Wl1, const float* __restrict__ Wr1)
{
    int idx = blockIdx.x * blockDim.x + threadIdx.x;
    int m   = idx >> 14;
    int rem = idx & 16383;
    int s   = rem >> 9;
    int g   = (rem >> 5) & 15;
    int l   = rem & 31;
    const float* W = (m == 0) ? Wl0 : (m == 1) ? Wr0 : (m == 2) ? Wl1 : Wr1;
    int k0 = 8 * s + (l & 3);
    int n0 = 16 * g + (l >> 2);
    float4 f;
    f.x = tf32r(W[k0 * EMBED + n0]);
    f.y = tf32r(W[(k0 + 4) * EMBED + n0]);
    f.z = tf32r(W[k0 * EMBED + n0 + 8]);
    f.w = tf32r(W[(k0 + 4) * EMBED + n0 + 8]);
    g_Wf[idx] = f;
}

// Fused dual GEMM, barrier-free: both Wl and Wr streamed from L2 with a
// one-slice register prefetch. DL = A@Wl + biasL; DR = A@Wr + biasR.
// SMALL: Wr path computes only rows node*8+7 (warps 0..7).
template <bool SMALL>
__device__ __forceinline__ void gemm_dual(
    const float4* __restrict__ WlF, const float* __restrict__ biasL,
    const float4* __restrict__ WrF, const float* __restrict__ biasR,
    const float* __restrict__ A, float* __restrict__ DL, float* __restrict__ DR,
    int tid)
{
    const int wid = tid >> 5, lane = tid & 31;
    const int mb = wid >> 3, nb = wid & 7;
    const int qr = lane >> 2, qk = lane & 3;
    const bool doR = !SMALL || wid < 8;

    float accL[8][4];
    float accR[8][4];
#pragma unroll
    for (int t = 0; t < 8; t++)
#pragma unroll
        for (int j = 0; j < 4; j++) { accL[t][j] = 0.f; accR[t][j] = 0.f; }

    // prefetch slice 0 fragments
    float4 pl0 = WlF[(nb * 2 + 0) * 32 + lane];
    float4 pl1 = WlF[(nb * 2 + 1) * 32 + lane];
    float4 pr0 = make_float4(0.f, 0.f, 0.f, 0.f), pr1 = pr0;
    if (doR) {
        pr0 = WrF[(nb * 2 + 0) * 32 + lane];
        pr1 = WrF[(nb * 2 + 1) * 32 + lane];
    }

#pragma unroll 2
    for (int s = 0; s < KSTEPS; s++) {
        float4 cl0 = pl0, cl1 = pl1, cr0 = pr0, cr1 = pr1;
        if (s + 1 < KSTEPS) {
            const float4* Wn = WlF + (s + 1) * SLICE_F4;
            pl0 = Wn[(nb * 2 + 0) * 32 + lane];
            pl1 = Wn[(nb * 2 + 1) * 32 + lane];
            if (doR) {
                const float4* Wm = WrF + (s + 1) * SLICE_F4;
                pr0 = Wm[(nb * 2 + 0) * 32 + lane];
                pr1 = Wm[(nb * 2 + 1) * 32 + lane];
            }
        }

        // A fragments (shared by both matrices)
        uint32_t a[2][4];
#pragma unroll
        for (int mt = 0; mt < 2; mt++) {
            const float* Ar  = A + (mb * 32 + mt * 16 + qr) * PITCH + s * 8;
            const float* Ar8 = Ar + 8 * PITCH;
            a[mt][0] = __float_as_uint(Ar[qk]);
            a[mt][1] = __float_as_uint(Ar8[qk]);
            a[mt][2] = __float_as_uint(Ar[qk + 4]);
            a[mt][3] = __float_as_uint(Ar8[qk + 4]);
        }
        uint32_t as[4];
        if (SMALL) {
            const float* Ar = A + (qr * 8 + 7) * PITCH + s * 8;
            as[0] = __float_as_uint(Ar[qk]);
            as[2] = __float_as_uint(Ar[qk + 4]);
            as[1] = as[0]; as[3] = as[2];
        }

        // Wl mma
        {
            uint32_t b[4][2];
            b[0][0] = __float_as_uint(cl0.x); b[0][1] = __float_as_uint(cl0.y);
            b[1][0] = __float_as_uint(cl0.z); b[1][1] = __float_as_uint(cl0.w);
            b[2][0] = __float_as_uint(cl1.x); b[2][1] = __float_as_uint(cl1.y);
            b[3][0] = __float_as_uint(cl1.z); b[3][1] = __float_as_uint(cl1.w);
#pragma unroll
            for (int mt = 0; mt < 2; mt++)
#pragma unroll
                for (int nt = 0; nt < 4; nt++) mma_tf32(accL[mt * 4 + nt], a[mt], b[nt]);
        }
        // Wr mma
        if (doR) {
            uint32_t b[4][2];
            b[0][0] = __float_as_uint(cr0.x); b[0][1] = __float_as_uint(cr0.y);
            b[1][0] = __float_as_uint(cr0.z); b[1][1] = __float_as_uint(cr0.w);
            b[2][0] = __float_as_uint(cr1.x); b[2][1] = __float_as_uint(cr1.y);
            b[3][0] = __float_as_uint(cr1.z); b[3][1] = __float_as_uint(cr1.w);
            if (!SMALL) {
#pragma unroll
                for (int mt = 0; mt < 2; mt++)
#pragma unroll
                    for (int nt = 0; nt < 4; nt++) mma_tf32(accR[mt * 4 + nt], a[mt], b[nt]);
            } else {
#pragma unroll
                for (int nt = 0; nt < 4; nt++) mma_tf32(accR[nt], as, b[nt]);
            }
        }
    }

    // epilogue (caller issues __syncthreads after)
#pragma unroll
    for (int mt = 0; mt < 2; mt++)
#pragma unroll
        for (int nt = 0; nt < 4; nt++) {
            int row = mb * 32 + mt * 16 + qr;
            int c0  = nb * 32 + nt * 8 + 2 * qk;
            float bx = biasL[c0], by = biasL[c0 + 1];
            float* d = DL + row * PITCH + c0;
            d[0] = accL[mt * 4 + nt][0] + bx;
            d[1] = accL[mt * 4 + nt][1] + by;
            d[8 * PITCH]     = accL[mt * 4 + nt][2] + bx;
            d[8 * PITCH + 1] = accL[mt * 4 + nt][3] + by;
        }
    if (!SMALL) {
#pragma unroll
        for (int mt = 0; mt < 2; mt++)
#pragma unroll
            for (int nt = 0; nt < 4; nt++) {
                int row = mb * 32 + mt * 16 + qr;
                int c0  = nb * 32 + nt * 8 + 2 * qk;
                float bx = biasR[c0], by = biasR[c0 + 1];
                float* d = DR + row * PITCH + c0;
                d[0] = accR[mt * 4 + nt][0] + bx;
                d[1] = accR[mt * 4 + nt][1] + by;
                d[8 * PITCH]     = accR[mt * 4 + nt][2] + bx;
                d[8 * PITCH + 1] = accR[mt * 4 + nt][3] + by;
            }
    } else if (wid < 8) {
#pragma unroll
        for (int nt = 0; nt < 4; nt++) {
            int c0 = nb * 32 + nt * 8 + 2 * qk;
            float* d = DR + (qr * 8 + 7) * PITCH + c0;
            d[0] = accR[nt][0] + biasR[c0];
            d[1] = accR[nt][1] + biasR[c0 + 1];
        }
    }
}

extern "C" __global__ void __launch_bounds__(NTHREADS, 1)
metapath_gat_kernel(
    const float* __restrict__ x,
    const float* __restrict__ bl0, const float* __restrict__ br0,
    const float* __restrict__ att0, const float* __restrict__ bias0,
    const float* __restrict__ bl1, const float* __restrict__ br1,
    const float* __restrict__ att1, const float* __restrict__ bias1,
    float* __restrict__ outEmb, float* __restrict__ outBeta)
{
    extern __shared__ float smem[];
    float* bufH     = smem;                          // [64][260]
    float* bufXL    = bufH + ROWS * PITCH;           // [64][260]
    float* bufXR    = bufXL + ROWS * PITCH;          // [64][260]
    float* partialS = bufXR + ROWS * PITCH;          // [64][8][8] = 4096
    float* alphaS   = partialS + 4096;               // 2048
    float* betaS    = alphaS + 2048;                 // 256
    float* attS     = betaS + 256;                   // 512

    const int tid = threadIdx.x;
    const int g = blockIdx.x;
    const float* xg = x + (size_t)g * (NB * RREL * EMBED);

    if (tid < 512) attS[tid] = (tid < 256) ? att0[tid] : att1[tid - 256];

    // Phase 1: x -> relu -> tf32 -> bufH
#pragma unroll
    for (int i = 0; i < 8; i++) {
        int idx = tid + i * NTHREADS;
        float4 v = reinterpret_cast<const float4*>(xg)[idx];
        int f = idx * 4;
        int r = f >> 8;
        int d = f & 255;
        v.x = tf32r(fmaxf(v.x, 0.f)); v.y = tf32r(fmaxf(v.y, 0.f));
        v.z = tf32r(fmaxf(v.z, 0.f)); v.w = tf32r(fmaxf(v.w, 0.f));
        *reinterpret_cast<float4*>(&bufH[r * PITCH + d]) = v;
    }
    __syncthreads();

    // Phase 2: fused layer-0 GEMMs (barrier-free mainloop)
    gemm_dual<false>(g_Wf + 0 * WMAT_F4, bl0, g_Wf + 1 * WMAT_F4, br0,
                     bufH, bufXL, bufXR, tid);
    __syncthreads();

    const int col  = tid & 255;
    const int half = tid >> 8;

    // Phase 3A: partial logits, i-register-blocked.
    // warp = (node, c-half); lane = (j, h); s[8] accumulates all dst i.
    {
        int w = tid >> 5, lane = tid & 31;
        int nd = w & 7, ch = w >> 3;
        int j = lane >> 2, h = lane & 3;
        const float* att = attS + h * 64;
        const float* xl  = bufXL + (nd * 8 + j) * PITCH + h * 64;
        const float* xrb = bufXR + (nd * 8) * PITCH + h * 64;
        float sa[8];
#pragma unroll
        for (int i = 0; i < 8; i++) sa[i] = 0.f;
        int c0 = ch * 32;
#pragma unroll 4
        for (int c = c0; c < c0 + 32; c++) {
            int cc = (c + h) & 63;          // bank-rotation: conflict-free xl
            float xlv = xl[cc];
            float av  = att[cc];
#pragma unroll
            for (int i = 0; i < 8; i++) {
                float xrv = xrb[i * PITCH + cc];
                sa[i] += av * leaky(xrv + xlv);
            }
        }
#pragma unroll
        for (int i = 0; i < 8; i++)
            partialS[((nd * 8 + i) * 8 + j) * 8 + ch * 4 + h] = sa[i];
    }
    __syncthreads();

    // Phase 3B: combine halves + softmax over j -> alphaS (warps 0..7)
    if (tid < 256) {
        int w = tid >> 5, lane = tid & 31;
        int nd = w, j = lane >> 2, h = lane & 3;
#pragma unroll
        for (int i = 0; i < 8; i++) {
            int base = ((nd * 8 + i) * 8 + j) * 8;
            float s = partialS[base + h] + partialS[base + 4 + h];
            float m = s;
            m = fmaxf(m, __shfl_xor_sync(0xffffffffu, m, 4));
            m = fmaxf(m, __shfl_xor_sync(0xffffffffu, m, 8));
            m = fmaxf(m, __shfl_xor_sync(0xffffffffu, m, 16));
            float e = __expf(s - m);
            float sum = e;
            sum += __shfl_xor_sync(0xffffffffu, sum, 4);
            sum += __shfl_xor_sync(0xffffffffu, sum, 8);
            sum += __shfl_xor_sync(0xffffffffu, sum, 16);
            alphaS[((nd * 8 + i) * 8 + j) * 4 + h] = e / sum;
        }
    }
    __syncthreads();

    // Phase 4: h1 = relu(alpha @ xl0 + bias0) -> bufH (tf32)
    {
        int h = col >> 6;
        float b0 = bias0[col];
#pragma unroll
        for (int nn = 0; nn < 4; nn++) {
            int nd = half * 4 + nn;
            float xlv[8];
#pragma unroll
            for (int j = 0; j < 8; j++) xlv[j] = bufXL[(nd * 8 + j) * PITCH + col];
#pragma unroll
            for (int i = 0; i < 8; i++) {
                float s = b0;
#pragma unroll
                for (int j = 0; j < 8; j++)
                    s += alphaS[((nd * 8 + i) * 8 + j) * 4 + h] * xlv[j];
                bufH[(nd * 8 + i) * PITCH + col] = tf32r(fmaxf(s, 0.f));
            }
        }
    }
    __syncthreads();

    // Phase 5: fused layer-1 GEMMs (xl1 full; xr1 self-rows)
    gemm_dual<true>(g_Wf + 2 * WMAT_F4, bl1, g_Wf + 3 * WMAT_F4, br1,
                    bufH, bufXL, bufXR, tid);
    __syncthreads();

    // Phase 6: logits1 + softmax over r -> beta
    if (tid < 256) {
        int node = tid >> 5, lane = tid & 31;
        int r = lane >> 2, h = lane & 3;
        const float* att = attS + 256 + h * 64;
        const float* xr = bufXR + (node * 8 + 7) * PITCH + h * 64;
        const float* xl = bufXL + (node * 8 + r) * PITCH + h * 64;
        float s = 0.f;
#pragma unroll 8
        for (int c = 0; c < 64; c++) {
            int cc = (c + h) & 63;
            s += att[cc] * leaky(xr[cc] + xl[cc]);
        }
        float m = s;
        m = fmaxf(m, __shfl_xor_sync(0xffffffffu, m, 4));
        m = fmaxf(m, __shfl_xor_sync(0xffffffffu, m, 8));
        m = fmaxf(m, __shfl_xor_sync(0xffffffffu, m, 16));
        float e = __expf(s - m);
        float sum = e;
        sum += __shfl_xor_sync(0xffffffffu, sum, 4);
        sum += __shfl_xor_sync(0xffffffffu, sum, 8);
        sum += __shfl_xor_sync(0xffffffffu, sum, 16);
        float beta = e / sum;
        betaS[(node * 8 + r) * 4 + h] = beta;
        outBeta[(size_t)(g * 8 + node) * 32 + r * 4 + h] = beta;
    }
    __syncthreads();

    // Phase 7: out = relu(beta @ xl1 + bias1)
    {
        int h = col >> 6;
        float b1 = bias1[col];
#pragma unroll
        for (int nn = 0; nn < 4; nn++) {
            int nd = half * 4 + nn;
            float s = b1;
#pragma unroll
            for (int r = 0; r < 8; r++)
                s += betaS[(nd * 8 + r) * 4 + h] * bufXL[(nd * 8 + r) * PITCH + col];
            outEmb[(size_t)(g * 8 + nd) * 256 + col] = fmaxf(s, 0.f);
        }
    }
}

extern "C" void kernel_launch(void* const* d_in, const int* in_sizes, int n_in,
                              void* d_out, int out_size)
{
    const float* x     = (const float*)d_in[0];
    const float* Wl0   = (const float*)d_in[1];
    const float* bl0   = (const float*)d_in[2];
    const float* Wr0   = (const float*)d_in[3];
    const float* br0   = (const float*)d_in[4];
    const float* att0  = (const float*)d_in[5];
    const float* bias0 = (const float*)d_in[6];
    const float* Wl1   = (const float*)d_in[7];
    const float* bl1   = (const float*)d_in[8];
    const float* Wr1   = (const float*)d_in[9];
    const float* br1   = (const float*)d_in[10];
    const float* att1  = (const float*)d_in[11];
    const float* bias1 = (const float*)d_in[12];

    int nodes = in_sizes[0] / (RREL * EMBED);
    float* outEmb  = (float*)d_out;
    float* outBeta = outEmb + (size_t)nodes * EMBED;

    repack_W<<<256, 256>>>(Wl0, Wr0, Wl1, Wr1);

    size_t smem_bytes = (size_t)(3 * ROWS * PITCH + 4096 + 2048 + 256 + 512)
                        * sizeof(float);
    cudaFuncSetAttribute(metapath_gat_kernel,
                         cudaFuncAttributeMaxDynamicSharedMemorySize,
                         (int)smem_bytes);

    metapath_gat_kernel<<<nodes / NB, NTHREADS, smem_bytes>>>(
        x, bl0, br0, att0, bias0, bl1, br1, att1, bias1, outEmb, outBeta);
}

// round 11
// speedup vs baseline: 1.0885x; 1.0885x over previous
#include <cuda_runtime.h>
#include <cstdint>

// MetapathGATConv fused kernel, R6: NB=4 nodes/CTA, 256 threads, 2 CTAs/SM.
// Barrier-free streamed-W tf32 mma GEMMs; in-warp logits+softmax.

#define RREL   8
#define EMBED  256
#define NB     4
#define ROWS   32            // NB * RREL
#define PITCH  260
#define NTHREADS 256
#define KSTEPS 32
#define SLICE_F4 512
#define WMAT_F4 (KSTEPS * SLICE_F4)

__device__ float4 g_Wf[4 * WMAT_F4];   // Wl0 | Wr0 | Wl1 | Wr1, fragment-major tf32

__device__ __forceinline__ float tf32r(float x) {
    uint32_t u;
    asm("cvt.rna.tf32.f32 %0, %1;" : "=r"(u) : "f"(x));
    return __uint_as_float(u);
}
__device__ __forceinline__ float leaky(float v) { return v > 0.f ? v : 0.2f * v; }

__device__ __forceinline__ void mma_tf32(float* c, const uint32_t* a, const uint32_t* b) {
    asm volatile(
        "mma.sync.aligned.m16n8k8.row.col.f32.tf32.tf32.f32 "
        "{%0,%1,%2,%3}, {%4,%5,%6,%7}, {%8,%9}, {%0,%1,%2,%3};"
        : "+f"(c[0]), "+f"(c[1]), "+f"(c[2]), "+f"(c[3])
        : "r"(a[0]), "r"(a[1]), "r"(a[2]), "r"(a[3]), "r"(b[0]), "r"(b[1]));
}

// W repack: Wf[mat][s][grp][lane] fragment-major tf32 (unchanged from R5).
__global__ void repack_W(const float* __restrict__ Wl0, const float* __restrict__ Wr0,
                         const float* __restrict__ Wl1, const float* __restrict__ Wr1)
{
    int idx = blockIdx.x * blockDim.x + threadIdx.x;
    int m   = idx >> 14;
    int rem = idx & 16383;
    int s   = rem >> 9;
    int g   = (rem >> 5) & 15;
    int l   = rem & 31;
    const float* W = (m == 0) ? Wl0 : (m == 1) ? Wr0 : (m == 2) ? Wl1 : Wr1;
    int k0 = 8 * s + (l & 3);
    int n0 = 16 * g + (l >> 2);
    float4 f;
    f.x = tf32r(W[k0 * EMBED + n0]);
    f.y = tf32r(W[(k0 + 4) * EMBED + n0]);
    f.z = tf32r(W[k0 * EMBED + n0 + 8]);
    f.w = tf32r(W[(k0 + 4) * EMBED + n0 + 8]);
    g_Wf[idx] = f;
}

// Fused dual GEMM over A[32,256], barrier-free, 8 warps (nb = wid, 32 cols each,
// both 16-row M-tiles per warp). DL = A@Wl + biasL (full). DR:
//   !SMALL -> full A@Wr + biasR
//   SMALL  -> rows node*8+7 only (node = qr<4), gathered A fragment.
template <bool SMALL>
__device__ __forceinline__ void gemm_dual(
    const float4* __restrict__ WlF, const float* __restrict__ biasL,
    const float4* __restrict__ WrF, const float* __restrict__ biasR,
    const float* __restrict__ A, float* __restrict__ DL, float* __restrict__ DR,
    int tid)
{
    const int nb = tid >> 5, lane = tid & 31;
    const int qr = lane >> 2, qk = lane & 3;

    float accL[8][4];
    float accR[8][4];
#pragma unroll
    for (int t = 0; t < 8; t++)
#pragma unroll
        for (int j = 0; j < 4; j++) { accL[t][j] = 0.f; accR[t][j] = 0.f; }

    // prefetch slice 0
    float4 pl0 = WlF[(nb * 2 + 0) * 32 + lane];
    float4 pl1 = WlF[(nb * 2 + 1) * 32 + lane];
    float4 pr0 = WrF[(nb * 2 + 0) * 32 + lane];
    float4 pr1 = WrF[(nb * 2 + 1) * 32 + lane];

#pragma unroll 2
    for (int s = 0; s < KSTEPS; s++) {
        float4 cl0 = pl0, cl1 = pl1, cr0 = pr0, cr1 = pr1;
        if (s + 1 < KSTEPS) {
            const float4* Wn = WlF + (s + 1) * SLICE_F4;
            const float4* Wm = WrF + (s + 1) * SLICE_F4;
            pl0 = Wn[(nb * 2 + 0) * 32 + lane];
            pl1 = Wn[(nb * 2 + 1) * 32 + lane];
            pr0 = Wm[(nb * 2 + 0) * 32 + lane];
            pr1 = Wm[(nb * 2 + 1) * 32 + lane];
        }

        // A fragments: rows mt*16+qr, mt*16+qr+8
        uint32_t a[2][4];
#pragma unroll
        for (int mt = 0; mt < 2; mt++) {
            const float* Ar  = A + (mt * 16 + qr) * PITCH + s * 8;
            const float* Ar8 = Ar + 8 * PITCH;
            a[mt][0] = __float_as_uint(Ar[qk]);
            a[mt][1] = __float_as_uint(Ar8[qk]);
            a[mt][2] = __float_as_uint(Ar[qk + 4]);
            a[mt][3] = __float_as_uint(Ar8[qk + 4]);
        }
        uint32_t as[4];
        if (SMALL) {
            const float* Ar = A + ((qr & 3) * 8 + 7) * PITCH + s * 8;
            as[0] = __float_as_uint(Ar[qk]);
            as[2] = __float_as_uint(Ar[qk + 4]);
            as[1] = as[0]; as[3] = as[2];
        }

        // Wl mma (8)
        {
            uint32_t b[4][2];
            b[0][0] = __float_as_uint(cl0.x); b[0][1] = __float_as_uint(cl0.y);
            b[1][0] = __float_as_uint(cl0.z); b[1][1] = __float_as_uint(cl0.w);
            b[2][0] = __float_as_uint(cl1.x); b[2][1] = __float_as_uint(cl1.y);
            b[3][0] = __float_as_uint(cl1.z); b[3][1] = __float_as_uint(cl1.w);
#pragma unroll
            for (int mt = 0; mt < 2; mt++)
#pragma unroll
                for (int nt = 0; nt < 4; nt++) mma_tf32(accL[mt * 4 + nt], a[mt], b[nt]);
        }
        // Wr mma (8 full / 4 small)
        {
            uint32_t b[4][2];
            b[0][0] = __float_as_uint(cr0.x); b[0][1] = __float_as_uint(cr0.y);
            b[1][0] = __float_as_uint(cr0.z); b[1][1] = __float_as_uint(cr0.w);
            b[2][0] = __float_as_uint(cr1.x); b[2][1] = __float_as_uint(cr1.y);
            b[3][0] = __float_as_uint(cr1.z); b[3][1] = __float_as_uint(cr1.w);
            if (!SMALL) {
#pragma unroll
                for (int mt = 0; mt < 2; mt++)
#pragma unroll
                    for (int nt = 0; nt < 4; nt++) mma_tf32(accR[mt * 4 + nt], a[mt], b[nt]);
            } else {
#pragma unroll
                for (int nt = 0; nt < 4; nt++) mma_tf32(accR[nt], as, b[nt]);
            }
        }
    }

    // epilogue (caller syncs after)
#pragma unroll
    for (int mt = 0; mt < 2; mt++)
#pragma unroll
        for (int nt = 0; nt < 4; nt++) {
            int row = mt * 16 + qr;
            int c0  = nb * 32 + nt * 8 + 2 * qk;
            float bx = biasL[c0], by = biasL[c0 + 1];
            float* d = DL + row * PITCH + c0;
            d[0] = accL[mt * 4 + nt][0] + bx;
            d[1] = accL[mt * 4 + nt][1] + by;
            d[8 * PITCH]     = accL[mt * 4 + nt][2] + bx;
            d[8 * PITCH + 1] = accL[mt * 4 + nt][3] + by;
        }
    if (!SMALL) {
#pragma unroll
        for (int mt = 0; mt < 2; mt++)
#pragma unroll
            for (int nt = 0; nt < 4; nt++) {
                int row = mt * 16 + qr;
                int c0  = nb * 32 + nt * 8 + 2 * qk;
                float bx = biasR[c0], by = biasR[c0 + 1];
                float* d = DR + row * PITCH + c0;
                d[0] = accR[mt * 4 + nt][0] + bx;
                d[1] = accR[mt * 4 + nt][1] + by;
                d[8 * PITCH]     = accR[mt * 4 + nt][2] + bx;
                d[8 * PITCH + 1] = accR[mt * 4 + nt][3] + by;
            }
    } else if (qr < 4) {
#pragma unroll
        for (int nt = 0; nt < 4; nt++) {
            int c0 = nb * 32 + nt * 8 + 2 * qk;
            float* d = DR + (qr * 8 + 7) * PITCH + c0;
            d[0] = accR[nt][0] + biasR[c0];
            d[1] = accR[nt][1] + biasR[c0 + 1];
        }
    }
}

extern "C" __global__ void __launch_bounds__(NTHREADS, 2)
metapath_gat_kernel(
    const float* __restrict__ x,
    const float* __restrict__ bl0, const float* __restrict__ br0,
    const float* __restrict__ att0, const float* __restrict__ bias0,
    const float* __restrict__ bl1, const float* __restrict__ br1,
    const float* __restrict__ att1, const float* __restrict__ bias1,
    float* __restrict__ outEmb, float* __restrict__ outBeta)
{
    extern __shared__ float smem[];
    float* bufH   = smem;                      // [32][260]
    float* bufXL  = bufH + ROWS * PITCH;       // [32][260]
    float* bufXR  = bufXL + ROWS * PITCH;      // [32][260]
    float* alphaS = bufXR + ROWS * PITCH;      // [4][8][8][4] = 1024
    float* betaS  = alphaS + 1024;             // [4][8][4]    = 128
    float* attS   = betaS + 128;               // 512

    const int tid = threadIdx.x;
    const int g = blockIdx.x;
    const float* xg = x + (size_t)g * (NB * RREL * EMBED);

    attS[tid]       = att0[tid];
    attS[tid + 256] = att1[tid];

    // Phase 1: x -> relu -> tf32 -> bufH  (2048 float4 / 256 thr)
#pragma unroll
    for (int i = 0; i < 8; i++) {
        int idx = tid + i * NTHREADS;
        float4 v = reinterpret_cast<const float4*>(xg)[idx];
        int f = idx * 4;
        int r = f >> 8;
        int d = f & 255;
        v.x = tf32r(fmaxf(v.x, 0.f)); v.y = tf32r(fmaxf(v.y, 0.f));
        v.z = tf32r(fmaxf(v.z, 0.f)); v.w = tf32r(fmaxf(v.w, 0.f));
        *reinterpret_cast<float4*>(&bufH[r * PITCH + d]) = v;
    }
    __syncthreads();

    // Phase 2: fused layer-0 GEMMs
    gemm_dual<false>(g_Wf + 0 * WMAT_F4, bl0, g_Wf + 1 * WMAT_F4, br0,
                     bufH, bufXL, bufXR, tid);
    __syncthreads();

    // Phase 3: logits0 + softmax over j. warp=(nd, ihalf); lane=(j,h); sa[4].
    {
        int w = tid >> 5, lane = tid & 31;
        int nd = w & 3, ihalf = w >> 2;
        int j = lane >> 2, h = lane & 3;
        const float* att = attS + h * 64;
        const float* xl  = bufXL + (nd * 8 + j) * PITCH + h * 64;
        const float* xrb = bufXR + (nd * 8 + ihalf * 4) * PITCH + h * 64;
        float sa[4];
#pragma unroll
        for (int ii = 0; ii < 4; ii++) sa[ii] = 0.f;
#pragma unroll 4
        for (int c = 0; c < 64; c++) {
            int cc = (c + h) & 63;           // bank-rotation: conflict-free
            float xlv = xl[cc];
            float av  = att[cc];
#pragma unroll
            for (int ii = 0; ii < 4; ii++)
                sa[ii] += av * leaky(xrb[ii * PITCH + cc] + xlv);
        }
#pragma unroll
        for (int ii = 0; ii < 4; ii++) {
            float s = sa[ii];
            float m = s;
            m = fmaxf(m, __shfl_xor_sync(0xffffffffu, m, 4));
            m = fmaxf(m, __shfl_xor_sync(0xffffffffu, m, 8));
            m = fmaxf(m, __shfl_xor_sync(0xffffffffu, m, 16));
            float e = __expf(s - m);
            float sum = e;
            sum += __shfl_xor_sync(0xffffffffu, sum, 4);
            sum += __shfl_xor_sync(0xffffffffu, sum, 8);
            sum += __shfl_xor_sync(0xffffffffu, sum, 16);
            alphaS[((nd * 8 + ihalf * 4 + ii) * 8 + j) * 4 + h] = e / sum;
        }
    }
    __syncthreads();

    // Phase 4: h1 = relu(alpha @ xl0 + bias0) -> bufH (tf32). col = tid.
    {
        int h = tid >> 6;
        float b0 = bias0[tid];
#pragma unroll
        for (int nd = 0; nd < NB; nd++) {
            float xlv[8];
#pragma unroll
            for (int j = 0; j < 8; j++) xlv[j] = bufXL[(nd * 8 + j) * PITCH + tid];
#pragma unroll
            for (int i = 0; i < 8; i++) {
                float s = b0;
#pragma unroll
                for (int j = 0; j < 8; j++)
                    s += alphaS[((nd * 8 + i) * 8 + j) * 4 + h] * xlv[j];
                bufH[(nd * 8 + i) * PITCH + tid] = tf32r(fmaxf(s, 0.f));
            }
        }
    }
    __syncthreads();

    // Phase 5: fused layer-1 GEMMs (xl1 full; xr1 self rows)
    gemm_dual<true>(g_Wf + 2 * WMAT_F4, bl1, g_Wf + 3 * WMAT_F4, br1,
                    bufH, bufXL, bufXR, tid);
    __syncthreads();

    // Phase 6: logits1 + softmax over r -> beta (tid<128: 4 nodes x 32 lanes)
    if (tid < 128) {
        int node = tid >> 5, lane = tid & 31;
        int r = lane >> 2, h = lane & 3;
        const float* att = attS + 256 + h * 64;
        const float* xr = bufXR + (node * 8 + 7) * PITCH + h * 64;
        const float* xl = bufXL + (node * 8 + r) * PITCH + h * 64;
        float s = 0.f;
#pragma unroll 8
        for (int c = 0; c < 64; c++) {
            int cc = (c + h) & 63;
            s += att[cc] * leaky(xr[cc] + xl[cc]);
        }
        float m = s;
        m = fmaxf(m, __shfl_xor_sync(0xffffffffu, m, 4));
        m = fmaxf(m, __shfl_xor_sync(0xffffffffu, m, 8));
        m = fmaxf(m, __shfl_xor_sync(0xffffffffu, m, 16));
        float e = __expf(s - m);
        float sum = e;
        sum += __shfl_xor_sync(0xffffffffu, sum, 4);
        sum += __shfl_xor_sync(0xffffffffu, sum, 8);
        sum += __shfl_xor_sync(0xffffffffu, sum, 16);
        float beta = e / sum;
        betaS[(node * 8 + r) * 4 + h] = beta;
        outBeta[(size_t)(g * NB + node) * 32 + r * 4 + h] = beta;
    }
    __syncthreads();

    // Phase 7: out = relu(beta @ xl1 + bias1). col = tid.
    {
        int h = tid >> 6;
        float b1 = bias1[tid];
#pragma unroll
        for (int nd = 0; nd < NB; nd++) {
            float s = b1;
#pragma unroll
            for (int r = 0; r < 8; r++)
                s += betaS[(nd * 8 + r) * 4 + h] * bufXL[(nd * 8 + r) * PITCH + tid];
            outEmb[(size_t)(g * NB + nd) * 256 + tid] = fmaxf(s, 0.f);
        }
    }
}

extern "C" void kernel_launch(void* const* d_in, const int* in_sizes, int n_in,
                              void* d_out, int out_size)
{
    const float* x     = (const float*)d_in[0];
    const float* Wl0   = (const float*)d_in[1];
    const float* bl0   = (const float*)d_in[2];
    const float* Wr0   = (const float*)d_in[3];
    const float* br0   = (const float*)d_in[4];
    const float* att0  = (const float*)d_in[5];
    const float* bias0 = (const float*)d_in[6];
    const float* Wl1   = (const float*)d_in[7];
    const float* bl1   = (const float*)d_in[8];
    const float* Wr1   = (const float*)d_in[9];
    const float* br1   = (const float*)d_in[10];
    const float* att1  = (const float*)d_in[11];
    const float* bias1 = (const float*)d_in[12];

    int nodes = in_sizes[0] / (RREL * EMBED);
    float* outEmb  = (float*)d_out;
    float* outBeta = outEmb + (size_t)nodes * EMBED;

    repack_W<<<256, 256>>>(Wl0, Wr0, Wl1, Wr1);

    size_t smem_bytes = (size_t)(3 * ROWS * PITCH + 1024 + 128 + 512) * sizeof(float);
    cudaFuncSetAttribute(metapath_gat_kernel,
                         cudaFuncAttributeMaxDynamicSharedMemorySize,
                         (int)smem_bytes);

    metapath_gat_kernel<<<nodes / NB, NTHREADS, smem_bytes>>>(
        x, bl0, br0, att0, bias0, bl1, br1, att1, bias1, outEmb, outBeta);
}

// round 12
// speedup vs baseline: 1.6524x; 1.5181x over previous
#include <cuda_runtime.h>
#include <cuda_fp16.h>
#include <cstdint>

// MetapathGATConv fused kernel, R7: fp16 m16n8k16 mma (fp32 accum).
// NB=4 nodes/CTA, 256 thr, 2 CTAs/SM. Barrier-free streamed-W GEMMs.
// bufH (GEMM A input) fp16; bufXL/XR (GEMM outputs, epilogue inputs) fp32.

#define RREL   8
#define EMBED  256
#define NB     4
#define ROWS   32            // NB * RREL
#define PITCH  260           // fp32 buf pitch (floats)
#define HP     264           // bufH pitch in halves (132 words, ==4 mod 32)
#define HPW    132           // bufH pitch in 32-bit words
#define NTHREADS 256
#define KSTEPS 16            // 256 / 16
#define WSLICE 64            // uint4 per (slice, nb): 2 q * 32 lanes
#define WMAT_U4 (KSTEPS * 8 * WSLICE)   // 8192 uint4 per matrix

__device__ uint4 g_Wh[4 * WMAT_U4];   // Wl0|Wr0|Wl1|Wr1, fp16 fragment-major

__device__ __forceinline__ uint32_t h2(float lo, float hi) {
    uint32_t r;
    asm("cvt.rn.f16x2.f32 %0, %1, %2;" : "=r"(r) : "f"(hi), "f"(lo));
    return r;
}
__device__ __forceinline__ float leaky(float v) { return v > 0.f ? v : 0.2f * v; }

__device__ __forceinline__ void mma_f16(float* c, const uint32_t* a,
                                        uint32_t b0, uint32_t b1) {
    asm volatile(
        "mma.sync.aligned.m16n8k16.row.col.f32.f16.f16.f32 "
        "{%0,%1,%2,%3}, {%4,%5,%6,%7}, {%8,%9}, {%0,%1,%2,%3};"
        : "+f"(c[0]), "+f"(c[1]), "+f"(c[2]), "+f"(c[3])
        : "r"(a[0]), "r"(a[1]), "r"(a[2]), "r"(a[3]), "r"(b0), "r"(b1));
}

// W repack into fp16 fragment-major.
// For (mat, s, nb, q, lane): lane = g*4+t; tiles nt = 2q+{0,1};
//   n = nb*32 + nt*8 + g; k0 = s*16 + 2t;
//   reg0 = half2(W[k0][n], W[k0+1][n]); reg1 = half2(W[k0+8][n], W[k0+9][n]);
// uint4 = {nt0.reg0, nt0.reg1, nt1.reg0, nt1.reg1}
__global__ void repack_W(const float* __restrict__ Wl0, const float* __restrict__ Wr0,
                         const float* __restrict__ Wl1, const float* __restrict__ Wr1)
{
    int idx = blockIdx.x * blockDim.x + threadIdx.x;   // 0..32767
    int m    = idx >> 13;
    int rem  = idx & 8191;
    int lane = rem & 31;
    int q    = (rem >> 5) & 1;
    int nb   = (rem >> 6) & 7;
    int s    = rem >> 9;
    int g = lane >> 2, t = lane & 3;
    const float* W = (m == 0) ? Wl0 : (m == 1) ? Wr0 : (m == 2) ? Wl1 : Wr1;

    uint32_t r[4];
#pragma unroll
    for (int e = 0; e < 2; e++) {
        int nt = q * 2 + e;
        int n  = nb * 32 + nt * 8 + g;
        int k0 = s * 16 + 2 * t;
        r[2 * e + 0] = h2(W[k0 * EMBED + n],       W[(k0 + 1) * EMBED + n]);
        r[2 * e + 1] = h2(W[(k0 + 8) * EMBED + n], W[(k0 + 9) * EMBED + n]);
    }
    g_Wh[idx] = make_uint4(r[0], r[1], r[2], r[3]);
}

// Fused dual GEMM over A[32,256] fp16 (word view Ah, pitch HPW), barrier-free.
// 8 warps: nb = wid owns cols nb*32..+31, both 16-row M tiles.
// DL = A@Wl + biasL (full, fp32 out). DR: !SMALL full; SMALL rows node*8+7 only.
template <bool SMALL>
__device__ __forceinline__ void gemm_dual(
    const uint4* __restrict__ WlF, const float* __restrict__ biasL,
    const uint4* __restrict__ WrF, const float* __restrict__ biasR,
    const uint32_t* __restrict__ Ah, float* __restrict__ DL, float* __restrict__ DR,
    int tid)
{
    const int nb = tid >> 5, lane = tid & 31;
    const int qr = lane >> 2, qk = lane & 3;

    float accL[8][4];
    float accR[8][4];
#pragma unroll
    for (int t = 0; t < 8; t++)
#pragma unroll
        for (int j = 0; j < 4; j++) { accL[t][j] = 0.f; accR[t][j] = 0.f; }

    // prefetch slice 0
    uint4 pl0 = WlF[(0 * 8 + nb) * WSLICE + lane];
    uint4 pl1 = WlF[(0 * 8 + nb) * WSLICE + 32 + lane];
    uint4 pr0 = WrF[(0 * 8 + nb) * WSLICE + lane];
    uint4 pr1 = WrF[(0 * 8 + nb) * WSLICE + 32 + lane];

#pragma unroll 2
    for (int s = 0; s < KSTEPS; s++) {
        uint4 cl0 = pl0, cl1 = pl1, cr0 = pr0, cr1 = pr1;
        if (s + 1 < KSTEPS) {
            pl0 = WlF[((s + 1) * 8 + nb) * WSLICE + lane];
            pl1 = WlF[((s + 1) * 8 + nb) * WSLICE + 32 + lane];
            pr0 = WrF[((s + 1) * 8 + nb) * WSLICE + lane];
            pr1 = WrF[((s + 1) * 8 + nb) * WSLICE + 32 + lane];
        }

        // A fragments: conflict-free LDS.32 (word = 132*row + s*8 + qk (+4))
        uint32_t a[2][4];
#pragma unroll
        for (int mt = 0; mt < 2; mt++) {
            int base  = (mt * 16 + qr) * HPW + s * 8;
            a[mt][0] = Ah[base + qk];
            a[mt][2] = Ah[base + qk + 4];
            a[mt][1] = Ah[base + 8 * HPW + qk];
            a[mt][3] = Ah[base + 8 * HPW + qk + 4];
        }
        uint32_t as[4];
        if (SMALL) {
            int base = ((qr & 3) * 8 + 7) * HPW + s * 8;
            as[0] = Ah[base + qk];
            as[2] = Ah[base + qk + 4];
            as[1] = as[0]; as[3] = as[2];
        }

        // Wl mma
#pragma unroll
        for (int mt = 0; mt < 2; mt++) {
            mma_f16(accL[mt * 4 + 0], a[mt], cl0.x, cl0.y);
            mma_f16(accL[mt * 4 + 1], a[mt], cl0.z, cl0.w);
            mma_f16(accL[mt * 4 + 2], a[mt], cl1.x, cl1.y);
            mma_f16(accL[mt * 4 + 3], a[mt], cl1.z, cl1.w);
        }
        // Wr mma
        if (!SMALL) {
#pragma unroll
            for (int mt = 0; mt < 2; mt++) {
                mma_f16(accR[mt * 4 + 0], a[mt], cr0.x, cr0.y);
                mma_f16(accR[mt * 4 + 1], a[mt], cr0.z, cr0.w);
                mma_f16(accR[mt * 4 + 2], a[mt], cr1.x, cr1.y);
                mma_f16(accR[mt * 4 + 3], a[mt], cr1.z, cr1.w);
            }
        } else {
            mma_f16(accR[0], as, cr0.x, cr0.y);
            mma_f16(accR[1], as, cr0.z, cr0.w);
            mma_f16(accR[2], as, cr1.x, cr1.y);
            mma_f16(accR[3], as, cr1.z, cr1.w);
        }
    }

    // epilogue (caller syncs after)
#pragma unroll
    for (int mt = 0; mt < 2; mt++)
#pragma unroll
        for (int nt = 0; nt < 4; nt++) {
            int row = mt * 16 + qr;
            int c0  = nb * 32 + nt * 8 + 2 * qk;
            float bx = biasL[c0], by = biasL[c0 + 1];
            float* d = DL + row * PITCH + c0;
            d[0] = accL[mt * 4 + nt][0] + bx;
            d[1] = accL[mt * 4 + nt][1] + by;
            d[8 * PITCH]     = accL[mt * 4 + nt][2] + bx;
            d[8 * PITCH + 1] = accL[mt * 4 + nt][3] + by;
        }
    if (!SMALL) {
#pragma unroll
        for (int mt = 0; mt < 2; mt++)
#pragma unroll
            for (int nt = 0; nt < 4; nt++) {
                int row = mt * 16 + qr;
                int c0  = nb * 32 + nt * 8 + 2 * qk;
                float bx = biasR[c0], by = biasR[c0 + 1];
                float* d = DR + row * PITCH + c0;
                d[0] = accR[mt * 4 + nt][0] + bx;
                d[1] = accR[mt * 4 + nt][1] + by;
                d[8 * PITCH]     = accR[mt * 4 + nt][2] + bx;
                d[8 * PITCH + 1] = accR[mt * 4 + nt][3] + by;
            }
    } else if (qr < 4) {
#pragma unroll
        for (int nt = 0; nt < 4; nt++) {
            int c0 = nb * 32 + nt * 8 + 2 * qk;
            float* d = DR + (qr * 8 + 7) * PITCH + c0;
            d[0] = accR[nt][0] + biasR[c0];
            d[1] = accR[nt][1] + biasR[c0 + 1];
        }
    }
}

extern "C" __global__ void __launch_bounds__(NTHREADS, 2)
metapath_gat_kernel(
    const float* __restrict__ x,
    const float* __restrict__ bl0, const float* __restrict__ br0,
    const float* __restrict__ att0, const float* __restrict__ bias0,
    const float* __restrict__ bl1, const float* __restrict__ br1,
    const float* __restrict__ att1, const float* __restrict__ bias1,
    float* __restrict__ outEmb, float* __restrict__ outBeta)
{
    extern __shared__ float smem[];
    uint32_t* bufHw = (uint32_t*)smem;          // fp16 [32][264 halves] = 4224 floats
    float* bufXL  = smem + ROWS * HPW;          // [32][260] fp32
    float* bufXR  = bufXL + ROWS * PITCH;       // [32][260] fp32
    float* alphaS = bufXR + ROWS * PITCH;       // 1024
    float* betaS  = alphaS + 1024;              // 128
    float* attS   = betaS + 128;                // 512

    const int tid = threadIdx.x;
    const int g = blockIdx.x;
    const float* xg = x + (size_t)g * (NB * RREL * EMBED);

    attS[tid]       = att0[tid];
    attS[tid + 256] = att1[tid];

    // Phase 1: x -> relu -> fp16 -> bufH
#pragma unroll
    for (int i = 0; i < 8; i++) {
        int idx = tid + i * NTHREADS;           // 0..2047 float4
        float4 v = reinterpret_cast<const float4*>(xg)[idx];
        int f = idx * 4;
        int r = f >> 8;
        int d = f & 255;
        uint2 p;
        p.x = h2(fmaxf(v.x, 0.f), fmaxf(v.y, 0.f));
        p.y = h2(fmaxf(v.z, 0.f), fmaxf(v.w, 0.f));
        *reinterpret_cast<uint2*>(bufHw + r * HPW + (d >> 1)) = p;
    }
    __syncthreads();

    // Phase 2: fused layer-0 GEMMs
    gemm_dual<false>(g_Wh + 0 * WMAT_U4, bl0, g_Wh + 1 * WMAT_U4, br0,
                     bufHw, bufXL, bufXR, tid);
    __syncthreads();

    // Phase 3: logits0 + softmax over j. warp=(nd, ihalf); lane=(j,h).
    {
        int w = tid >> 5, lane = tid & 31;
        int nd = w & 3, ihalf = w >> 2;
        int j = lane >> 2, h = lane & 3;
        const float* att = attS + h * 64;
        const float* xl  = bufXL + (nd * 8 + j) * PITCH + h * 64;
        const float* xrb = bufXR + (nd * 8 + ihalf * 4) * PITCH + h * 64;
        float sa[4];
#pragma unroll
        for (int ii = 0; ii < 4; ii++) sa[ii] = 0.f;
#pragma unroll 4
        for (int c = 0; c < 64; c++) {
            int cc = (c + h) & 63;              // bank-rotation: conflict-free
            float xlv = xl[cc];
            float av  = att[cc];
#pragma unroll
            for (int ii = 0; ii < 4; ii++)
                sa[ii] += av * leaky(xrb[ii * PITCH + cc] + xlv);
        }
#pragma unroll
        for (int ii = 0; ii < 4; ii++) {
            float s = sa[ii];
            float m = s;
            m = fmaxf(m, __shfl_xor_sync(0xffffffffu, m, 4));
            m = fmaxf(m, __shfl_xor_sync(0xffffffffu, m, 8));
            m = fmaxf(m, __shfl_xor_sync(0xffffffffu, m, 16));
            float e = __expf(s - m);
            float sum = e;
            sum += __shfl_xor_sync(0xffffffffu, sum, 4);
            sum += __shfl_xor_sync(0xffffffffu, sum, 8);
            sum += __shfl_xor_sync(0xffffffffu, sum, 16);
            alphaS[((nd * 8 + ihalf * 4 + ii) * 8 + j) * 4 + h] = e / sum;
        }
    }
    __syncthreads();

    // Phase 4: h1 = relu(alpha @ xl0 + bias0) -> bufH fp16.
    // thread -> col pair c0=2*(tid&127); nodes split by tid>>7.
    {
        int c0 = 2 * (tid & 127);
        int ndb = (tid >> 7) * 2;
        int h = c0 >> 6;
        float b0a = bias0[c0], b0b = bias0[c0 + 1];
#pragma unroll
        for (int nn = 0; nn < 2; nn++) {
            int nd = ndb + nn;
            float xa[8], xb[8];
#pragma unroll
            for (int j = 0; j < 8; j++) {
                float2 v = *reinterpret_cast<const float2*>(
                    bufXL + (nd * 8 + j) * PITCH + c0);
                xa[j] = v.x; xb[j] = v.y;
            }
#pragma unroll
            for (int i = 0; i < 8; i++) {
                float sa = b0a, sb = b0b;
#pragma unroll
                for (int j = 0; j < 8; j++) {
                    float al = alphaS[((nd * 8 + i) * 8 + j) * 4 + h];
                    sa += al * xa[j];
                    sb += al * xb[j];
                }
                bufHw[(nd * 8 + i) * HPW + (c0 >> 1)] =
                    h2(fmaxf(sa, 0.f), fmaxf(sb, 0.f));
            }
        }
    }
    __syncthreads();

    // Phase 5: fused layer-1 GEMMs (xl1 full; xr1 self rows)
    gemm_dual<true>(g_Wh + 2 * WMAT_U4, bl1, g_Wh + 3 * WMAT_U4, br1,
                    bufHw, bufXL, bufXR, tid);
    __syncthreads();

    // Phase 6: logits1 + softmax over r -> beta
    if (tid < 128) {
        int node = tid >> 5, lane = tid & 31;
        int r = lane >> 2, h = lane & 3;
        const float* att = attS + 256 + h * 64;
        const float* xr = bufXR + (node * 8 + 7) * PITCH + h * 64;
        const float* xl = bufXL + (node * 8 + r) * PITCH + h * 64;
        float s = 0.f;
#pragma unroll 8
        for (int c = 0; c < 64; c++) {
            int cc = (c + h) & 63;
            s += att[cc] * leaky(xr[cc] + xl[cc]);
        }
        float m = s;
        m = fmaxf(m, __shfl_xor_sync(0xffffffffu, m, 4));
        m = fmaxf(m, __shfl_xor_sync(0xffffffffu, m, 8));
        m = fmaxf(m, __shfl_xor_sync(0xffffffffu, m, 16));
        float e = __expf(s - m);
        float sum = e;
        sum += __shfl_xor_sync(0xffffffffu, sum, 4);
        sum += __shfl_xor_sync(0xffffffffu, sum, 8);
        sum += __shfl_xor_sync(0xffffffffu, sum, 16);
        float beta = e / sum;
        betaS[(node * 8 + r) * 4 + h] = beta;
        outBeta[(size_t)(g * NB + node) * 32 + r * 4 + h] = beta;
    }
    __syncthreads();

    // Phase 7: out = relu(beta @ xl1 + bias1). col = tid.
    {
        int h = tid >> 6;
        float b1 = bias1[tid];
#pragma unroll
        for (int nd = 0; nd < NB; nd++) {
            float s = b1;
#pragma unroll
            for (int r = 0; r < 8; r++)
                s += betaS[(nd * 8 + r) * 4 + h] * bufXL[(nd * 8 + r) * PITCH + tid];
            outEmb[(size_t)(g * NB + nd) * 256 + tid] = fmaxf(s, 0.f);
        }
    }
}

extern "C" void kernel_launch(void* const* d_in, const int* in_sizes, int n_in,
                              void* d_out, int out_size)
{
    const float* x     = (const float*)d_in[0];
    const float* Wl0   = (const float*)d_in[1];
    const float* bl0   = (const float*)d_in[2];
    const float* Wr0   = (const float*)d_in[3];
    const float* br0   = (const float*)d_in[4];
    const float* att0  = (const float*)d_in[5];
    const float* bias0 = (const float*)d_in[6];
    const float* Wl1   = (const float*)d_in[7];
    const float* bl1   = (const float*)d_in[8];
    const float* Wr1   = (const float*)d_in[9];
    const float* br1   = (const float*)d_in[10];
    const float* att1  = (const float*)d_in[11];
    const float* bias1 = (const float*)d_in[12];

    int nodes = in_sizes[0] / (RREL * EMBED);
    float* outEmb  = (float*)d_out;
    float* outBeta = outEmb + (size_t)nodes * EMBED;

    repack_W<<<128, 256>>>(Wl0, Wr0, Wl1, Wr1);

    size_t smem_bytes = (size_t)(ROWS * HPW + 2 * ROWS * PITCH + 1024 + 128 + 512)
                        * sizeof(float);
    cudaFuncSetAttribute(metapath_gat_kernel,
                         cudaFuncAttributeMaxDynamicSharedMemorySize,
                         (int)smem_bytes);

    metapath_gat_kernel<<<nodes / NB, NTHREADS, smem_bytes>>>(
        x, bl0, br0, att0, bias0, bl1, br1, att1, bias1, outEmb, outBeta);
}

// round 13
// speedup vs baseline: 1.7496x; 1.0588x over previous
#include <cuda_runtime.h>
#include <cuda_fp16.h>
#include <cstdint>

// MetapathGATConv fused kernel, R8: all-fp16 SMEM intermediates.
// fp16 m16n8k16 mma (fp32 accum), NB=4 nodes/CTA, 256 thr, 2 CTAs/SM.
// bufH, bufXL, bufXR, alpha, att all fp16 in SMEM; all math fp32.

#define RREL   8
#define EMBED  256
#define NB     4
#define ROWS   32            // NB * RREL
#define HPW    132           // fp16 buffer pitch in 32-bit words (== 4 mod 32)
#define NTHREADS 256
#define KSTEPS 16            // 256 / 16
#define WSLICE 64            // uint4 per (slice, nb)
#define WMAT_U4 (KSTEPS * 8 * WSLICE)   // 8192 uint4 per matrix

__device__ uint4 g_Wh[4 * WMAT_U4];   // Wl0|Wr0|Wl1|Wr1, fp16 fragment-major

__device__ __forceinline__ uint32_t h2(float lo, float hi) {
    uint32_t r;
    asm("cvt.rn.f16x2.f32 %0, %1, %2;" : "=r"(r) : "f"(hi), "f"(lo));
    return r;
}
__device__ __forceinline__ float2 up2(uint32_t w) {
    __half2 hv = *reinterpret_cast<__half2*>(&w);
    return __half22float2(hv);
}
__device__ __forceinline__ float leaky(float v) { return v > 0.f ? v : 0.2f * v; }

__device__ __forceinline__ void mma_f16(float* c, const uint32_t* a,
                                        uint32_t b0, uint32_t b1) {
    asm volatile(
        "mma.sync.aligned.m16n8k16.row.col.f32.f16.f16.f32 "
        "{%0,%1,%2,%3}, {%4,%5,%6,%7}, {%8,%9}, {%0,%1,%2,%3};"
        : "+f"(c[0]), "+f"(c[1]), "+f"(c[2]), "+f"(c[3])
        : "r"(a[0]), "r"(a[1]), "r"(a[2]), "r"(a[3]), "r"(b0), "r"(b1));
}

// W repack into fp16 fragment-major (unchanged from R7).
__global__ void repack_W(const float* __restrict__ Wl0, const float* __restrict__ Wr0,
                         const float* __restrict__ Wl1, const float* __restrict__ Wr1)
{
    int idx = blockIdx.x * blockDim.x + threadIdx.x;   // 0..32767
    int m    = idx >> 13;
    int rem  = idx & 8191;
    int lane = rem & 31;
    int q    = (rem >> 5) & 1;
    int nb   = (rem >> 6) & 7;
    int s    = rem >> 9;
    int g = lane >> 2, t = lane & 3;
    const float* W = (m == 0) ? Wl0 : (m == 1) ? Wr0 : (m == 2) ? Wl1 : Wr1;

    uint32_t r[4];
#pragma unroll
    for (int e = 0; e < 2; e++) {
        int nt = q * 2 + e;
        int n  = nb * 32 + nt * 8 + g;
        int k0 = s * 16 + 2 * t;
        r[2 * e + 0] = h2(W[k0 * EMBED + n],       W[(k0 + 1) * EMBED + n]);
        r[2 * e + 1] = h2(W[(k0 + 8) * EMBED + n], W[(k0 + 9) * EMBED + n]);
    }
    g_Wh[idx] = make_uint4(r[0], r[1], r[2], r[3]);
}

// Fused dual GEMM over A[32,256] fp16 (word view Ah, pitch HPW), barrier-free.
// Outputs DL/DR are fp16 word buffers (pitch HPW).
template <bool SMALL>
__device__ __forceinline__ void gemm_dual(
    const uint4* __restrict__ WlF, const float* __restrict__ biasL,
    const uint4* __restrict__ WrF, const float* __restrict__ biasR,
    const uint32_t* __restrict__ Ah, uint32_t* __restrict__ DL,
    uint32_t* __restrict__ DR, int tid)
{
    const int nb = tid >> 5, lane = tid & 31;
    const int qr = lane >> 2, qk = lane & 3;

    float accL[8][4];
    float accR[8][4];
#pragma unroll
    for (int t = 0; t < 8; t++)
#pragma unroll
        for (int j = 0; j < 4; j++) { accL[t][j] = 0.f; accR[t][j] = 0.f; }

    uint4 pl0 = WlF[(0 * 8 + nb) * WSLICE + lane];
    uint4 pl1 = WlF[(0 * 8 + nb) * WSLICE + 32 + lane];
    uint4 pr0 = WrF[(0 * 8 + nb) * WSLICE + lane];
    uint4 pr1 = WrF[(0 * 8 + nb) * WSLICE + 32 + lane];

#pragma unroll 2
    for (int s = 0; s < KSTEPS; s++) {
        uint4 cl0 = pl0, cl1 = pl1, cr0 = pr0, cr1 = pr1;
        if (s + 1 < KSTEPS) {
            pl0 = WlF[((s + 1) * 8 + nb) * WSLICE + lane];
            pl1 = WlF[((s + 1) * 8 + nb) * WSLICE + 32 + lane];
            pr0 = WrF[((s + 1) * 8 + nb) * WSLICE + lane];
            pr1 = WrF[((s + 1) * 8 + nb) * WSLICE + 32 + lane];
        }

        uint32_t a[2][4];
#pragma unroll
        for (int mt = 0; mt < 2; mt++) {
            int base  = (mt * 16 + qr) * HPW + s * 8;
            a[mt][0] = Ah[base + qk];
            a[mt][2] = Ah[base + qk + 4];
            a[mt][1] = Ah[base + 8 * HPW + qk];
            a[mt][3] = Ah[base + 8 * HPW + qk + 4];
        }
        uint32_t as[4];
        if (SMALL) {
            int base = ((qr & 3) * 8 + 7) * HPW + s * 8;
            as[0] = Ah[base + qk];
            as[2] = Ah[base + qk + 4];
            as[1] = as[0]; as[3] = as[2];
        }

#pragma unroll
        for (int mt = 0; mt < 2; mt++) {
            mma_f16(accL[mt * 4 + 0], a[mt], cl0.x, cl0.y);
            mma_f16(accL[mt * 4 + 1], a[mt], cl0.z, cl0.w);
            mma_f16(accL[mt * 4 + 2], a[mt], cl1.x, cl1.y);
            mma_f16(accL[mt * 4 + 3], a[mt], cl1.z, cl1.w);
        }
        if (!SMALL) {
#pragma unroll
            for (int mt = 0; mt < 2; mt++) {
                mma_f16(accR[mt * 4 + 0], a[mt], cr0.x, cr0.y);
                mma_f16(accR[mt * 4 + 1], a[mt], cr0.z, cr0.w);
                mma_f16(accR[mt * 4 + 2], a[mt], cr1.x, cr1.y);
                mma_f16(accR[mt * 4 + 3], a[mt], cr1.z, cr1.w);
            }
        } else {
            mma_f16(accR[0], as, cr0.x, cr0.y);
            mma_f16(accR[1], as, cr0.z, cr0.w);
            mma_f16(accR[2], as, cr1.x, cr1.y);
            mma_f16(accR[3], as, cr1.z, cr1.w);
        }
    }

    // epilogue: pack to fp16 words (1 STS.32 per col-pair), conflict-free
#pragma unroll
    for (int mt = 0; mt < 2; mt++)
#pragma unroll
        for (int nt = 0; nt < 4; nt++) {
            int c0 = nb * 32 + nt * 8 + 2 * qk;
            int wc = nb * 16 + nt * 4 + qk;
            float bx = biasL[c0], by = biasL[c0 + 1];
            DL[(mt * 16 + qr) * HPW + wc] =
                h2(accL[mt * 4 + nt][0] + bx, accL[mt * 4 + nt][1] + by);
            DL[(mt * 16 + qr + 8) * HPW + wc] =
                h2(accL[mt * 4 + nt][2] + bx, accL[mt * 4 + nt][3] + by);
        }
    if (!SMALL) {
#pragma unroll
        for (int mt = 0; mt < 2; mt++)
#pragma unroll
            for (int nt = 0; nt < 4; nt++) {
                int c0 = nb * 32 + nt * 8 + 2 * qk;
                int wc = nb * 16 + nt * 4 + qk;
                float bx = biasR[c0], by = biasR[c0 + 1];
                DR[(mt * 16 + qr) * HPW + wc] =
                    h2(accR[mt * 4 + nt][0] + bx, accR[mt * 4 + nt][1] + by);
                DR[(mt * 16 + qr + 8) * HPW + wc] =
                    h2(accR[mt * 4 + nt][2] + bx, accR[mt * 4 + nt][3] + by);
            }
    } else if (qr < 4) {
#pragma unroll
        for (int nt = 0; nt < 4; nt++) {
            int c0 = nb * 32 + nt * 8 + 2 * qk;
            int wc = nb * 16 + nt * 4 + qk;
            DR[(qr * 8 + 7) * HPW + wc] =
                h2(accR[nt][0] + biasR[c0], accR[nt][1] + biasR[c0 + 1]);
        }
    }
}

extern "C" __global__ void __launch_bounds__(NTHREADS, 2)
metapath_gat_kernel(
    const float* __restrict__ x,
    const float* __restrict__ bl0, const float* __restrict__ br0,
    const float* __restrict__ att0, const float* __restrict__ bias0,
    const float* __restrict__ bl1, const float* __restrict__ br1,
    const float* __restrict__ att1, const float* __restrict__ bias1,
    float* __restrict__ outEmb, float* __restrict__ outBeta)
{
    extern __shared__ uint32_t smemw[];
    uint32_t* bufHw  = smemw;                    // [32][132] fp16 words
    uint32_t* bufXLw = bufHw  + ROWS * HPW;      // [32][132]
    uint32_t* bufXRw = bufXLw + ROWS * HPW;      // [32][132]
    uint32_t* alphaW = bufXRw + ROWS * HPW;      // 256 words: [nd][i][h][j] halves
    float*    betaS  = (float*)(alphaW + 256);   // 128 floats
    uint32_t* attH0  = (uint32_t*)(betaS + 128); // [4][32] half2 words
    uint32_t* attH1  = attH0 + 128;              // [4][32]

    __half* alphaH = (__half*)alphaW;

    const int tid = threadIdx.x;
    const int g = blockIdx.x;
    const float* xg = x + (size_t)g * (NB * RREL * EMBED);

    if (tid < 128) {
        attH0[tid] = h2(att0[2 * tid], att0[2 * tid + 1]);
        attH1[tid] = h2(att1[2 * tid], att1[2 * tid + 1]);
    }

    // Phase 1: x -> relu -> fp16 -> bufH
#pragma unroll
    for (int i = 0; i < 8; i++) {
        int idx = tid + i * NTHREADS;           // 0..2047 float4
        float4 v = reinterpret_cast<const float4*>(xg)[idx];
        int f = idx * 4;
        int r = f >> 8;
        int d = f & 255;
        uint2 p;
        p.x = h2(fmaxf(v.x, 0.f), fmaxf(v.y, 0.f));
        p.y = h2(fmaxf(v.z, 0.f), fmaxf(v.w, 0.f));
        *reinterpret_cast<uint2*>(bufHw + r * HPW + (d >> 1)) = p;
    }
    __syncthreads();

    // Phase 2: fused layer-0 GEMMs
    gemm_dual<false>(g_Wh + 0 * WMAT_U4, bl0, g_Wh + 1 * WMAT_U4, br0,
                     bufHw, bufXLw, bufXRw, tid);
    __syncthreads();

    // Phase 3: logits0 + softmax over j. warp=(nd, ihalf); lane=(j,h).
    {
        int w = tid >> 5, lane = tid & 31;
        int nd = w & 3, ihalf = w >> 2;
        int j = lane >> 2, h = lane & 3;
        const uint32_t* at2 = attH0 + h * 32;
        const uint32_t* xl2 = bufXLw + (nd * 8 + j) * HPW + h * 32;
        const uint32_t* xr2 = bufXRw + (nd * 8 + ihalf * 4) * HPW + h * 32;
        float sa[4];
#pragma unroll
        for (int ii = 0; ii < 4; ii++) sa[ii] = 0.f;
#pragma unroll 4
        for (int c2 = 0; c2 < 32; c2++) {
            int cc = (c2 + h) & 31;             // half2-unit rotation: conflict-free
            float2 xlv = up2(xl2[cc]);
            float2 av  = up2(at2[cc]);
#pragma unroll
            for (int ii = 0; ii < 4; ii++) {
                float2 xrv = up2(xr2[ii * HPW + cc]);
                sa[ii] += av.x * leaky(xrv.x + xlv.x)
                        + av.y * leaky(xrv.y + xlv.y);
            }
        }
#pragma unroll
        for (int ii = 0; ii < 4; ii++) {
            float s = sa[ii];
            float m = s;
            m = fmaxf(m, __shfl_xor_sync(0xffffffffu, m, 4));
            m = fmaxf(m, __shfl_xor_sync(0xffffffffu, m, 8));
            m = fmaxf(m, __shfl_xor_sync(0xffffffffu, m, 16));
            float e = __expf(s - m);
            float sum = e;
            sum += __shfl_xor_sync(0xffffffffu, sum, 4);
            sum += __shfl_xor_sync(0xffffffffu, sum, 8);
            sum += __shfl_xor_sync(0xffffffffu, sum, 16);
            alphaH[((nd * 8 + ihalf * 4 + ii) * 4 + h) * 8 + j] =
                __float2half(e / sum);
        }
    }
    __syncthreads();

    // Phase 4: h1 = relu(alpha @ xl0 + bias0) -> bufH fp16.
    {
        int c0 = 2 * (tid & 127);
        int ndb = (tid >> 7) * 2;
        int h = c0 >> 6;
        float b0a = bias0[c0], b0b = bias0[c0 + 1];
#pragma unroll
        for (int nn = 0; nn < 2; nn++) {
            int nd = ndb + nn;
            float xa[8], xb[8];
#pragma unroll
            for (int j = 0; j < 8; j++) {
                float2 v = up2(bufXLw[(nd * 8 + j) * HPW + (c0 >> 1)]);
                xa[j] = v.x; xb[j] = v.y;
            }
#pragma unroll
            for (int i = 0; i < 8; i++) {
                uint2 aw = *reinterpret_cast<const uint2*>(
                    alphaW + ((nd * 8 + i) * 4 + h) * 4);
                float2 a01 = up2(aw.x), a23 = up2(aw.x >> 32 ? aw.x : aw.x);
                // unpack 8 alphas: words aw.x (j0..j3? no: 2 halves/word)
                float2 p0 = up2(aw.x);
                float2 p1 = up2(aw.y);
                uint2 aw2 = *reinterpret_cast<const uint2*>(
                    alphaW + ((nd * 8 + i) * 4 + h) * 4 + 2);
                float2 p2 = up2(aw2.x);
                float2 p3 = up2(aw2.y);
                float al[8] = {p0.x, p0.y, p1.x, p1.y, p2.x, p2.y, p3.x, p3.y};
                float sa = b0a, sb = b0b;
#pragma unroll
                for (int j = 0; j < 8; j++) {
                    sa += al[j] * xa[j];
                    sb += al[j] * xb[j];
                }
                bufHw[(nd * 8 + i) * HPW + (c0 >> 1)] =
                    h2(fmaxf(sa, 0.f), fmaxf(sb, 0.f));
            }
        }
    }
    __syncthreads();

    // Phase 5: fused layer-1 GEMMs (xl1 full; xr1 self rows)
    gemm_dual<true>(g_Wh + 2 * WMAT_U4, bl1, g_Wh + 3 * WMAT_U4, br1,
                    bufHw, bufXLw, bufXRw, tid);
    __syncthreads();

    // Phase 6: logits1 + softmax over r -> beta
    if (tid < 128) {
        int node = tid >> 5, lane = tid & 31;
        int r = lane >> 2, h = lane & 3;
        const uint32_t* at2 = attH1 + h * 32;
        const uint32_t* xr2 = bufXRw + (node * 8 + 7) * HPW + h * 32;
        const uint32_t* xl2 = bufXLw + (node * 8 + r) * HPW + h * 32;
        float s = 0.f;
#pragma unroll 4
        for (int c2 = 0; c2 < 32; c2++) {
            int cc = (c2 + h) & 31;
            float2 xlv = up2(xl2[cc]);
            float2 xrv = up2(xr2[cc]);
            float2 av  = up2(at2[cc]);
            s += av.x * leaky(xrv.x + xlv.x) + av.y * leaky(xrv.y + xlv.y);
        }
        float m = s;
        m = fmaxf(m, __shfl_xor_sync(0xffffffffu, m, 4));
        m = fmaxf(m, __shfl_xor_sync(0xffffffffu, m, 8));
        m = fmaxf(m, __shfl_xor_sync(0xffffffffu, m, 16));
        float e = __expf(s - m);
        float sum = e;
        sum += __shfl_xor_sync(0xffffffffu, sum, 4);
        sum += __shfl_xor_sync(0xffffffffu, sum, 8);
        sum += __shfl_xor_sync(0xffffffffu, sum, 16);
        float beta = e / sum;
        betaS[(node * 8 + r) * 4 + h] = beta;
        outBeta[(size_t)(g * NB + node) * 32 + r * 4 + h] = beta;
    }
    __syncthreads();

    // Phase 7: out = relu(beta @ xl1 + bias1). col = tid.
    {
        int h = tid >> 6;
        const __half* xlh = (const __half*)bufXLw;
        float b1 = bias1[tid];
#pragma unroll
        for (int nd = 0; nd < NB; nd++) {
            float s = b1;
#pragma unroll
            for (int r = 0; r < 8; r++)
                s += betaS[(nd * 8 + r) * 4 + h] *
                     __half2float(xlh[(nd * 8 + r) * (2 * HPW) + tid]);
            outEmb[(size_t)(g * NB + nd) * 256 + tid] = fmaxf(s, 0.f);
        }
    }
}

extern "C" void kernel_launch(void* const* d_in, const int* in_sizes, int n_in,
                              void* d_out, int out_size)
{
    const float* x     = (const float*)d_in[0];
    const float* Wl0   = (const float*)d_in[1];
    const float* bl0   = (const float*)d_in[2];
    const float* Wr0   = (const float*)d_in[3];
    const float* br0   = (const float*)d_in[4];
    const float* att0  = (const float*)d_in[5];
    const float* bias0 = (const float*)d_in[6];
    const float* Wl1   = (const float*)d_in[7];
    const float* bl1   = (const float*)d_in[8];
    const float* Wr1   = (const float*)d_in[9];
    const float* br1   = (const float*)d_in[10];
    const float* att1  = (const float*)d_in[11];
    const float* bias1 = (const float*)d_in[12];

    int nodes = in_sizes[0] / (RREL * EMBED);
    float* outEmb  = (float*)d_out;
    float* outBeta = outEmb + (size_t)nodes * EMBED;

    repack_W<<<128, 256>>>(Wl0, Wr0, Wl1, Wr1);

    size_t smem_bytes = (size_t)(3 * ROWS * HPW + 256 + 128 + 128 + 128) * 4;
    cudaFuncSetAttribute(metapath_gat_kernel,
                         cudaFuncAttributeMaxDynamicSharedMemorySize,
                         (int)smem_bytes);

    metapath_gat_kernel<<<nodes / NB, NTHREADS, smem_bytes>>>(
        x, bl0, br0, att0, bias0, bl1, br1, att1, bias1, outEmb, outBeta);
}

// round 14
// speedup vs baseline: 1.7604x; 1.0062x over previous
#include <cuda_runtime.h>
#include <cuda_fp16.h>
#include <cstdint>

// MetapathGATConv fused kernel, R9: precision-consolidated hybrid.
// fp16 m16n8k16 mma (fp32 accum), NB=4 nodes/CTA, 256 thr, 2 CTAs/SM.
// bufH/xr/att/xl(logit-copy) fp16; xl(aggregation-copy)/alpha/beta fp32.
// ldmatrix.x4 for A fragments.

#define RREL   8
#define EMBED  256
#define NB     4
#define ROWS   32            // NB * RREL
#define HPW    132           // fp16 buffer pitch in 32-bit words (== 4 mod 32)
#define FPW    260           // fp32 xl pitch in floats
#define NTHREADS 256
#define KSTEPS 16            // 256 / 16
#define WSLICE 64            // uint4 per (slice, nb)
#define WMAT_U4 (KSTEPS * 8 * WSLICE)   // 8192 uint4 per matrix

__device__ uint4 g_Wh[4 * WMAT_U4];   // Wl0|Wr0|Wl1|Wr1, fp16 fragment-major

__device__ __forceinline__ uint32_t h2(float lo, float hi) {
    uint32_t r;
    asm("cvt.rn.f16x2.f32 %0, %1, %2;" : "=r"(r) : "f"(hi), "f"(lo));
    return r;
}
__device__ __forceinline__ float2 up2(uint32_t w) {
    __half2 hv = *reinterpret_cast<__half2*>(&w);
    return __half22float2(hv);
}
__device__ __forceinline__ float leaky(float v) { return v > 0.f ? v : 0.2f * v; }

__device__ __forceinline__ void mma_f16(float* c, const uint32_t* a,
                                        uint32_t b0, uint32_t b1) {
    asm volatile(
        "mma.sync.aligned.m16n8k16.row.col.f32.f16.f16.f32 "
        "{%0,%1,%2,%3}, {%4,%5,%6,%7}, {%8,%9}, {%0,%1,%2,%3};"
        : "+f"(c[0]), "+f"(c[1]), "+f"(c[2]), "+f"(c[3])
        : "r"(a[0]), "r"(a[1]), "r"(a[2]), "r"(a[3]), "r"(b0), "r"(b1));
}
__device__ __forceinline__ void ldsm_x4(uint32_t* a, uint32_t smaddr) {
    asm volatile("ldmatrix.sync.aligned.m8n8.x4.shared.b16 {%0,%1,%2,%3}, [%4];"
                 : "=r"(a[0]), "=r"(a[1]), "=r"(a[2]), "=r"(a[3]) : "r"(smaddr));
}

// W repack into fp16 fragment-major (unchanged from R7/R8).
__global__ void repack_W(const float* __restrict__ Wl0, const float* __restrict__ Wr0,
                         const float* __restrict__ Wl1, const float* __restrict__ Wr1)
{
    int idx = blockIdx.x * blockDim.x + threadIdx.x;   // 0..32767
    int m    = idx >> 13;
    int rem  = idx & 8191;
    int lane = rem & 31;
    int q    = (rem >> 5) & 1;
    int nb   = (rem >> 6) & 7;
    int s    = rem >> 9;
    int g = lane >> 2, t = lane & 3;
    const float* W = (m == 0) ? Wl0 : (m == 1) ? Wr0 : (m == 2) ? Wl1 : Wr1;

    uint32_t r[4];
#pragma unroll
    for (int e = 0; e < 2; e++) {
        int nt = q * 2 + e;
        int n  = nb * 32 + nt * 8 + g;
        int k0 = s * 16 + 2 * t;
        r[2 * e + 0] = h2(W[k0 * EMBED + n],       W[(k0 + 1) * EMBED + n]);
        r[2 * e + 1] = h2(W[(k0 + 8) * EMBED + n], W[(k0 + 9) * EMBED + n]);
    }
    g_Wh[idx] = make_uint4(r[0], r[1], r[2], r[3]);
}

// Fused dual GEMM over A[32,256] fp16, barrier-free, ldmatrix A frags.
// DL -> fp16 copy (DLh, pitch HPW) AND fp32 copy (DLf, pitch FPW).
// DR -> fp16 only (DRh). SMALL: DR rows node*8+7 only.
template <bool SMALL>
__device__ __forceinline__ void gemm_dual(
    const uint4* __restrict__ WlF, const float* __restrict__ biasL,
    const uint4* __restrict__ WrF, const float* __restrict__ biasR,
    const uint32_t* __restrict__ Ah, uint32_t* __restrict__ DLh,
    float* __restrict__ DLf, uint32_t* __restrict__ DRh, int tid)
{
    const int nb = tid >> 5, lane = tid & 31;
    const int qr = lane >> 2, qk = lane & 3;
    const int lrow = ((lane >> 3) & 1) * 8 + (lane & 7);   // ldmatrix row-in-tilepair
    const int lcol = (lane >> 4) * 4;                      // ldmatrix k-half (words)
    const uint32_t abase = (uint32_t)__cvta_generic_to_shared(Ah);

    float accL[8][4];
    float accR[8][4];
#pragma unroll
    for (int t = 0; t < 8; t++)
#pragma unroll
        for (int j = 0; j < 4; j++) { accL[t][j] = 0.f; accR[t][j] = 0.f; }

    uint4 pl0 = WlF[(0 * 8 + nb) * WSLICE + lane];
    uint4 pl1 = WlF[(0 * 8 + nb) * WSLICE + 32 + lane];
    uint4 pr0 = WrF[(0 * 8 + nb) * WSLICE + lane];
    uint4 pr1 = WrF[(0 * 8 + nb) * WSLICE + 32 + lane];

#pragma unroll 2
    for (int s = 0; s < KSTEPS; s++) {
        uint4 cl0 = pl0, cl1 = pl1, cr0 = pr0, cr1 = pr1;
        if (s + 1 < KSTEPS) {
            pl0 = WlF[((s + 1) * 8 + nb) * WSLICE + lane];
            pl1 = WlF[((s + 1) * 8 + nb) * WSLICE + 32 + lane];
            pr0 = WrF[((s + 1) * 8 + nb) * WSLICE + lane];
            pr1 = WrF[((s + 1) * 8 + nb) * WSLICE + 32 + lane];
        }

        uint32_t a[2][4];
#pragma unroll
        for (int mt = 0; mt < 2; mt++)
            ldsm_x4(a[mt], abase + 4u * ((mt * 16 + lrow) * HPW + s * 8 + lcol));

        uint32_t as[4];
        if (SMALL) {
            int base = ((qr & 3) * 8 + 7) * HPW + s * 8;
            as[0] = Ah[base + qk];
            as[2] = Ah[base + qk + 4];
            as[1] = as[0]; as[3] = as[2];
        }

#pragma unroll
        for (int mt = 0; mt < 2; mt++) {
            mma_f16(accL[mt * 4 + 0], a[mt], cl0.x, cl0.y);
            mma_f16(accL[mt * 4 + 1], a[mt], cl0.z, cl0.w);
            mma_f16(accL[mt * 4 + 2], a[mt], cl1.x, cl1.y);
            mma_f16(accL[mt * 4 + 3], a[mt], cl1.z, cl1.w);
        }
        if (!SMALL) {
#pragma unroll
            for (int mt = 0; mt < 2; mt++) {
                mma_f16(accR[mt * 4 + 0], a[mt], cr0.x, cr0.y);
                mma_f16(accR[mt * 4 + 1], a[mt], cr0.z, cr0.w);
                mma_f16(accR[mt * 4 + 2], a[mt], cr1.x, cr1.y);
                mma_f16(accR[mt * 4 + 3], a[mt], cr1.z, cr1.w);
            }
        } else {
            mma_f16(accR[0], as, cr0.x, cr0.y);
            mma_f16(accR[1], as, cr0.z, cr0.w);
            mma_f16(accR[2], as, cr1.x, cr1.y);
            mma_f16(accR[3], as, cr1.z, cr1.w);
        }
    }

    // epilogue: DL dual store (fp16 + fp32); DR fp16.
#pragma unroll
    for (int mt = 0; mt < 2; mt++)
#pragma unroll
        for (int nt = 0; nt < 4; nt++) {
            int c0 = nb * 32 + nt * 8 + 2 * qk;
            int wc = c0 >> 1;
            float bx = biasL[c0], by = biasL[c0 + 1];
            float v0 = accL[mt * 4 + nt][0] + bx;
            float v1 = accL[mt * 4 + nt][1] + by;
            float v2 = accL[mt * 4 + nt][2] + bx;
            float v3 = accL[mt * 4 + nt][3] + by;
            DLh[(mt * 16 + qr) * HPW + wc]     = h2(v0, v1);
            DLh[(mt * 16 + qr + 8) * HPW + wc] = h2(v2, v3);
            *reinterpret_cast<float2*>(DLf + (mt * 16 + qr) * FPW + c0) =
                make_float2(v0, v1);
            *reinterpret_cast<float2*>(DLf + (mt * 16 + qr + 8) * FPW + c0) =
                make_float2(v2, v3);
        }
    if (!SMALL) {
#pragma unroll
        for (int mt = 0; mt < 2; mt++)
#pragma unroll
            for (int nt = 0; nt < 4; nt++) {
                int c0 = nb * 32 + nt * 8 + 2 * qk;
                int wc = c0 >> 1;
                float bx = biasR[c0], by = biasR[c0 + 1];
                DRh[(mt * 16 + qr) * HPW + wc] =
                    h2(accR[mt * 4 + nt][0] + bx, accR[mt * 4 + nt][1] + by);
                DRh[(mt * 16 + qr + 8) * HPW + wc] =
                    h2(accR[mt * 4 + nt][2] + bx, accR[mt * 4 + nt][3] + by);
            }
    } else if (qr < 4) {
#pragma unroll
        for (int nt = 0; nt < 4; nt++) {
            int c0 = nb * 32 + nt * 8 + 2 * qk;
            int wc = c0 >> 1;
            DRh[(qr * 8 + 7) * HPW + wc] =
                h2(accR[nt][0] + biasR[c0], accR[nt][1] + biasR[c0 + 1]);
        }
    }
}

extern "C" __global__ void __launch_bounds__(NTHREADS, 2)
metapath_gat_kernel(
    const float* __restrict__ x,
    const float* __restrict__ bl0, const float* __restrict__ br0,
    const float* __restrict__ att0, const float* __restrict__ bias0,
    const float* __restrict__ bl1, const float* __restrict__ br1,
    const float* __restrict__ att1, const float* __restrict__ bias1,
    float* __restrict__ outEmb, float* __restrict__ outBeta)
{
    extern __shared__ uint32_t smemw[];
    uint32_t* bufHw  = smemw;                     // [32][132] fp16 words
    uint32_t* bufXRw = bufHw  + ROWS * HPW;       // [32][132] fp16 (xr)
    uint32_t* bufXLh = bufXRw + ROWS * HPW;       // [32][132] fp16 xl (logits copy)
    float*    bufXLf = (float*)(bufXLh + ROWS * HPW);  // [32][260] fp32 xl
    float*    alphaS = bufXLf + ROWS * FPW;       // [nd][i][h][j] fp32 = 1024
    float*    betaS  = alphaS + 1024;             // 128
    uint32_t* attH0  = (uint32_t*)(betaS + 128);  // [4][32] half2 words
    uint32_t* attH1  = attH0 + 128;

    const int tid = threadIdx.x;
    const int g = blockIdx.x;
    const float* xg = x + (size_t)g * (NB * RREL * EMBED);

    if (tid < 128) {
        attH0[tid] = h2(att0[2 * tid], att0[2 * tid + 1]);
        attH1[tid] = h2(att1[2 * tid], att1[2 * tid + 1]);
    }

    // Phase 1: x -> relu -> fp16 -> bufH
#pragma unroll
    for (int i = 0; i < 8; i++) {
        int idx = tid + i * NTHREADS;             // 0..2047 float4
        float4 v = reinterpret_cast<const float4*>(xg)[idx];
        int f = idx * 4;
        int r = f >> 8;
        int d = f & 255;
        uint2 p;
        p.x = h2(fmaxf(v.x, 0.f), fmaxf(v.y, 0.f));
        p.y = h2(fmaxf(v.z, 0.f), fmaxf(v.w, 0.f));
        *reinterpret_cast<uint2*>(bufHw + r * HPW + (d >> 1)) = p;
    }
    __syncthreads();

    // Phase 2: fused layer-0 GEMMs
    gemm_dual<false>(g_Wh + 0 * WMAT_U4, bl0, g_Wh + 1 * WMAT_U4, br0,
                     bufHw, bufXLh, bufXLf, bufXRw, tid);
    __syncthreads();

    // Phase 3: logits0 + softmax over j. warp=(nd, ihalf); lane=(j,h).
    {
        int w = tid >> 5, lane = tid & 31;
        int nd = w & 3, ihalf = w >> 2;
        int j = lane >> 2, h = lane & 3;
        const uint32_t* at2 = attH0 + h * 32;
        const uint32_t* xl2 = bufXLh + (nd * 8 + j) * HPW + h * 32;
        const uint32_t* xr2 = bufXRw + (nd * 8 + ihalf * 4) * HPW + h * 32;
        float sa[4];
#pragma unroll
        for (int ii = 0; ii < 4; ii++) sa[ii] = 0.f;
#pragma unroll 4
        for (int c2 = 0; c2 < 32; c2++) {
            int cc = (c2 + h) & 31;               // half2-unit rotation
            float2 xlv = up2(xl2[cc]);
            float2 av  = up2(at2[cc]);
#pragma unroll
            for (int ii = 0; ii < 4; ii++) {
                float2 xrv = up2(xr2[ii * HPW + cc]);
                sa[ii] += av.x * leaky(xrv.x + xlv.x)
                        + av.y * leaky(xrv.y + xlv.y);
            }
        }
#pragma unroll
        for (int ii = 0; ii < 4; ii++) {
            float s = sa[ii];
            float m = s;
            m = fmaxf(m, __shfl_xor_sync(0xffffffffu, m, 4));
            m = fmaxf(m, __shfl_xor_sync(0xffffffffu, m, 8));
            m = fmaxf(m, __shfl_xor_sync(0xffffffffu, m, 16));
            float e = __expf(s - m);
            float sum = e;
            sum += __shfl_xor_sync(0xffffffffu, sum, 4);
            sum += __shfl_xor_sync(0xffffffffu, sum, 8);
            sum += __shfl_xor_sync(0xffffffffu, sum, 16);
            alphaS[((nd * 8 + ihalf * 4 + ii) * 4 + h) * 8 + j] = e / sum;
        }
    }
    __syncthreads();

    // Phase 4: h1 = relu(alpha @ xl0 + bias0) -> bufH fp16 (fp32 inputs).
    {
        int c0 = 2 * (tid & 127);
        int ndb = (tid >> 7) * 2;
        int h = c0 >> 6;
        float b0a = bias0[c0], b0b = bias0[c0 + 1];
#pragma unroll
        for (int nn = 0; nn < 2; nn++) {
            int nd = ndb + nn;
            float xa[8], xb[8];
#pragma unroll
            for (int j = 0; j < 8; j++) {
                float2 v = *reinterpret_cast<const float2*>(
                    bufXLf + (nd * 8 + j) * FPW + c0);
                xa[j] = v.x; xb[j] = v.y;
            }
#pragma unroll
            for (int i = 0; i < 8; i++) {
                const float4* ap = reinterpret_cast<const float4*>(
                    alphaS + ((nd * 8 + i) * 4 + h) * 8);
                float4 a03 = ap[0];
                float4 a47 = ap[1];
                float al[8] = {a03.x, a03.y, a03.z, a03.w,
                               a47.x, a47.y, a47.z, a47.w};
                float sa = b0a, sb = b0b;
#pragma unroll
                for (int j = 0; j < 8; j++) {
                    sa += al[j] * xa[j];
                    sb += al[j] * xb[j];
                }
                bufHw[(nd * 8 + i) * HPW + (c0 >> 1)] =
                    h2(fmaxf(sa, 0.f), fmaxf(sb, 0.f));
            }
        }
    }
    __syncthreads();

    // Phase 5: fused layer-1 GEMMs (xl1 full; xr1 self rows)
    gemm_dual<true>(g_Wh + 2 * WMAT_U4, bl1, g_Wh + 3 * WMAT_U4, br1,
                    bufHw, bufXLh, bufXLf, bufXRw, tid);
    __syncthreads();

    // Phase 6: logits1 + softmax over r -> beta (xl fp32, xr/att fp16)
    if (tid < 128) {
        int node = tid >> 5, lane = tid & 31;
        int r = lane >> 2, h = lane & 3;
        const uint32_t* at2 = attH1 + h * 32;
        const uint32_t* xr2 = bufXRw + (node * 8 + 7) * HPW + h * 32;
        const float*    xl  = bufXLf + (node * 8 + r) * FPW + h * 64;
        float s = 0.f;
#pragma unroll 4
        for (int c2 = 0; c2 < 32; c2++) {
            int cc = (c2 + h) & 31;
            float2 xrv = up2(xr2[cc]);
            float2 av  = up2(at2[cc]);
            float2 xlv = *reinterpret_cast<const float2*>(xl + 2 * cc);
            s += av.x * leaky(xrv.x + xlv.x) + av.y * leaky(xrv.y + xlv.y);
        }
        float m = s;
        m = fmaxf(m, __shfl_xor_sync(0xffffffffu, m, 4));
        m = fmaxf(m, __shfl_xor_sync(0xffffffffu, m, 8));
        m = fmaxf(m, __shfl_xor_sync(0xffffffffu, m, 16));
        float e = __expf(s - m);
        float sum = e;
        sum += __shfl_xor_sync(0xffffffffu, sum, 4);
        sum += __shfl_xor_sync(0xffffffffu, sum, 8);
        sum += __shfl_xor_sync(0xffffffffu, sum, 16);
        float beta = e / sum;
        betaS[(node * 8 + r) * 4 + h] = beta;
        outBeta[(size_t)(g * NB + node) * 32 + r * 4 + h] = beta;
    }
    __syncthreads();

    // Phase 7: out = relu(beta @ xl1 + bias1), xl fp32. col = tid.
    {
        int h = tid >> 6;
        float b1 = bias1[tid];
#pragma unroll
        for (int nd = 0; nd < NB; nd++) {
            float s = b1;
#pragma unroll
            for (int r = 0; r < 8; r++)
                s += betaS[(nd * 8 + r) * 4 + h] * bufXLf[(nd * 8 + r) * FPW + tid];
            outEmb[(size_t)(g * NB + nd) * 256 + tid] = fmaxf(s, 0.f);
        }
    }
}

extern "C" void kernel_launch(void* const* d_in, const int* in_sizes, int n_in,
                              void* d_out, int out_size)
{
    const float* x     = (const float*)d_in[0];
    const float* Wl0   = (const float*)d_in[1];
    const float* bl0   = (const float*)d_in[2];
    const float* Wr0   = (const float*)d_in[3];
    const float* br0   = (const float*)d_in[4];
    const float* att0  = (const float*)d_in[5];
    const float* bias0 = (const float*)d_in[6];
    const float* Wl1   = (const float*)d_in[7];
    const float* bl1   = (const float*)d_in[8];
    const float* Wr1   = (const float*)d_in[9];
    const float* br1   = (const float*)d_in[10];
    const float* att1  = (const float*)d_in[11];
    const float* bias1 = (const float*)d_in[12];

    int nodes = in_sizes[0] / (RREL * EMBED);
    float* outEmb  = (float*)d_out;
    float* outBeta = outEmb + (size_t)nodes * EMBED;

    repack_W<<<128, 256>>>(Wl0, Wr0, Wl1, Wr1);

    size_t smem_words = 3 * ROWS * HPW + ROWS * FPW + 1024 + 128 + 256;
    size_t smem_bytes = smem_words * 4;
    cudaFuncSetAttribute(metapath_gat_kernel,
                         cudaFuncAttributeMaxDynamicSharedMemorySize,
                         (int)smem_bytes);

    metapath_gat_kernel<<<nodes / NB, NTHREADS, smem_bytes>>>(
        x, bl0, br0, att0, bias0, bl1, br1, att1, bias1, outEmb, outBeta);
}

// round 16
// speedup vs baseline: 1.8533x; 1.0528x over previous
#include <cuda_runtime.h>
#include <cuda_fp16.h>
#include <cstdint>

// MetapathGATConv fused kernel, R10: 256-bit W/x loads (LDG.E.256),
// half2 logits with LDS.64. fp16 m16n8k16 mma (fp32 accum), NB=4, 256 thr,
// 2 CTAs/SM. bufH/xr/att/xl-logit fp16; xl-aggregation/alpha/beta fp32.

#define RREL   8
#define EMBED  256
#define NB     4
#define ROWS   32            // NB * RREL
#define HPW    132           // fp16 buffer pitch in 32-bit words (== 4 mod 32)
#define FPW    260           // fp32 xl pitch in floats
#define NTHREADS 256
#define KSTEPS 16            // 256 / 16
#define WMAT_U4 (KSTEPS * 8 * 64)   // 8192 uint4 per matrix

__device__ uint4 g_Wh[4 * WMAT_U4];   // Wl0|Wr0|Wl1|Wr1, fp16 pair-contiguous frags

__device__ __forceinline__ uint32_t h2(float lo, float hi) {
    uint32_t r;
    asm("cvt.rn.f16x2.f32 %0, %1, %2;" : "=r"(r) : "f"(hi), "f"(lo));
    return r;
}
__device__ __forceinline__ __half2 u2h(uint32_t w) {
    return *reinterpret_cast<__half2*>(&w);
}
__device__ __forceinline__ float leaky(float v) { return v > 0.f ? v : 0.2f * v; }

__device__ __forceinline__ void ldg256(uint32_t* r, const void* p) {
    asm volatile("ld.global.nc.v8.b32 {%0,%1,%2,%3,%4,%5,%6,%7}, [%8];"
        : "=r"(r[0]), "=r"(r[1]), "=r"(r[2]), "=r"(r[3]),
          "=r"(r[4]), "=r"(r[5]), "=r"(r[6]), "=r"(r[7])
        : "l"(p));
}
__device__ __forceinline__ void mma_f16(float* c, const uint32_t* a,
                                        uint32_t b0, uint32_t b1) {
    asm volatile(
        "mma.sync.aligned.m16n8k16.row.col.f32.f16.f16.f32 "
        "{%0,%1,%2,%3}, {%4,%5,%6,%7}, {%8,%9}, {%0,%1,%2,%3};"
        : "+f"(c[0]), "+f"(c[1]), "+f"(c[2]), "+f"(c[3])
        : "r"(a[0]), "r"(a[1]), "r"(a[2]), "r"(a[3]), "r"(b0), "r"(b1));
}
__device__ __forceinline__ void ldsm_x4(uint32_t* a, uint32_t smaddr) {
    asm volatile("ldmatrix.sync.aligned.m8n8.x4.shared.b16 {%0,%1,%2,%3}, [%4];"
                 : "=r"(a[0]), "=r"(a[1]), "=r"(a[2]), "=r"(a[3]) : "r"(smaddr));
}

// W repack, pair-contiguous: uint4 index within matrix = ((s*8+nb)*32+lane)*2+q.
__global__ void repack_W(const float* __restrict__ Wl0, const float* __restrict__ Wr0,
                         const float* __restrict__ Wl1, const float* __restrict__ Wr1)
{
    int idx = blockIdx.x * blockDim.x + threadIdx.x;   // 0..32767
    int q    = idx & 1;
    int lane = (idx >> 1) & 31;
    int nb   = (idx >> 6) & 7;
    int s    = (idx >> 9) & 15;
    int m    = idx >> 13;
    int g = lane >> 2, t = lane & 3;
    const float* W = (m == 0) ? Wl0 : (m == 1) ? Wr0 : (m == 2) ? Wl1 : Wr1;

    uint32_t r[4];
#pragma unroll
    for (int e = 0; e < 2; e++) {
        int nt = q * 2 + e;
        int n  = nb * 32 + nt * 8 + g;
        int k0 = s * 16 + 2 * t;
        r[2 * e + 0] = h2(W[k0 * EMBED + n],       W[(k0 + 1) * EMBED + n]);
        r[2 * e + 1] = h2(W[(k0 + 8) * EMBED + n], W[(k0 + 9) * EMBED + n]);
    }
    g_Wh[idx] = make_uint4(r[0], r[1], r[2], r[3]);
}

// Fused dual GEMM over A[32,256] fp16, barrier-free, ldmatrix A frags,
// v8 W loads. DL -> fp16 (DLh) + fp32 (DLf). DR fp16; SMALL: rows node*8+7.
template <bool SMALL>
__device__ __forceinline__ void gemm_dual(
    const uint4* __restrict__ WlF, const float* __restrict__ biasL,
    const uint4* __restrict__ WrF, const float* __restrict__ biasR,
    const uint32_t* __restrict__ Ah, uint32_t* __restrict__ DLh,
    float* __restrict__ DLf, uint32_t* __restrict__ DRh, int tid)
{
    const int nb = tid >> 5, lane = tid & 31;
    const int qr = lane >> 2, qk = lane & 3;
    const int lrow = ((lane >> 3) & 1) * 8 + (lane & 7);
    const int lcol = (lane >> 4) * 4;
    const uint32_t abase = (uint32_t)__cvta_generic_to_shared(Ah);

    float accL[8][4];
    float accR[8][4];
#pragma unroll
    for (int t = 0; t < 8; t++)
#pragma unroll
        for (int j = 0; j < 4; j++) { accL[t][j] = 0.f; accR[t][j] = 0.f; }

    uint32_t wlA[8], wrA[8], wlB[8], wrB[8];
    ldg256(wlA, WlF + (0 * 8 + nb) * 64 + lane * 2);
    ldg256(wrA, WrF + (0 * 8 + nb) * 64 + lane * 2);

    auto body = [&](int s, const uint32_t* wl, const uint32_t* wr) {
        uint32_t a[2][4];
#pragma unroll
        for (int mt = 0; mt < 2; mt++)
            ldsm_x4(a[mt], abase + 4u * ((mt * 16 + lrow) * HPW + s * 8 + lcol));

        uint32_t as[4];
        if (SMALL) {
            int base = ((qr & 3) * 8 + 7) * HPW + s * 8;
            as[0] = Ah[base + qk];
            as[2] = Ah[base + qk + 4];
            as[1] = as[0]; as[3] = as[2];
        }
#pragma unroll
        for (int mt = 0; mt < 2; mt++) {
            mma_f16(accL[mt * 4 + 0], a[mt], wl[0], wl[1]);
            mma_f16(accL[mt * 4 + 1], a[mt], wl[2], wl[3]);
            mma_f16(accL[mt * 4 + 2], a[mt], wl[4], wl[5]);
            mma_f16(accL[mt * 4 + 3], a[mt], wl[6], wl[7]);
        }
        if (!SMALL) {
#pragma unroll
            for (int mt = 0; mt < 2; mt++) {
                mma_f16(accR[mt * 4 + 0], a[mt], wr[0], wr[1]);
                mma_f16(accR[mt * 4 + 1], a[mt], wr[2], wr[3]);
                mma_f16(accR[mt * 4 + 2], a[mt], wr[4], wr[5]);
                mma_f16(accR[mt * 4 + 3], a[mt], wr[6], wr[7]);
            }
        } else {
            mma_f16(accR[0], as, wr[0], wr[1]);
            mma_f16(accR[1], as, wr[2], wr[3]);
            mma_f16(accR[2], as, wr[4], wr[5]);
            mma_f16(accR[3], as, wr[6], wr[7]);
        }
    };

#pragma unroll
    for (int s = 0; s < KSTEPS; s += 2) {
        ldg256(wlB, WlF + ((s + 1) * 8 + nb) * 64 + lane * 2);
        ldg256(wrB, WrF + ((s + 1) * 8 + nb) * 64 + lane * 2);
        body(s, wlA, wrA);
        if (s + 2 < KSTEPS) {
            ldg256(wlA, WlF + ((s + 2) * 8 + nb) * 64 + lane * 2);
            ldg256(wrA, WrF + ((s + 2) * 8 + nb) * 64 + lane * 2);
        }
        body(s + 1, wlB, wrB);
    }

    // epilogue: DL dual store (fp16 + fp32); DR fp16.
#pragma unroll
    for (int mt = 0; mt < 2; mt++)
#pragma unroll
        for (int nt = 0; nt < 4; nt++) {
            int c0 = nb * 32 + nt * 8 + 2 * qk;
            int wc = c0 >> 1;
            float bx = biasL[c0], by = biasL[c0 + 1];
            float v0 = accL[mt * 4 + nt][0] + bx;
            float v1 = accL[mt * 4 + nt][1] + by;
            float v2 = accL[mt * 4 + nt][2] + bx;
            float v3 = accL[mt * 4 + nt][3] + by;
            DLh[(mt * 16 + qr) * HPW + wc]     = h2(v0, v1);
            DLh[(mt * 16 + qr + 8) * HPW + wc] = h2(v2, v3);
            *reinterpret_cast<float2*>(DLf + (mt * 16 + qr) * FPW + c0) =
                make_float2(v0, v1);
            *reinterpret_cast<float2*>(DLf + (mt * 16 + qr + 8) * FPW + c0) =
                make_float2(v2, v3);
        }
    if (!SMALL) {
#pragma unroll
        for (int mt = 0; mt < 2; mt++)
#pragma unroll
            for (int nt = 0; nt < 4; nt++) {
                int c0 = nb * 32 + nt * 8 + 2 * qk;
                int wc = c0 >> 1;
                float bx = biasR[c0], by = biasR[c0 + 1];
                DRh[(mt * 16 + qr) * HPW + wc] =
                    h2(accR[mt * 4 + nt][0] + bx, accR[mt * 4 + nt][1] + by);
                DRh[(mt * 16 + qr + 8) * HPW + wc] =
                    h2(accR[mt * 4 + nt][2] + bx, accR[mt * 4 + nt][3] + by);
            }
    } else if (qr < 4) {
#pragma unroll
        for (int nt = 0; nt < 4; nt++) {
            int c0 = nb * 32 + nt * 8 + 2 * qk;
            int wc = c0 >> 1;
            DRh[(qr * 8 + 7) * HPW + wc] =
                h2(accR[nt][0] + biasR[c0], accR[nt][1] + biasR[c0 + 1]);
        }
    }
}

extern "C" __global__ void __launch_bounds__(NTHREADS, 2)
metapath_gat_kernel(
    const float* __restrict__ x,
    const float* __restrict__ bl0, const float* __restrict__ br0,
    const float* __restrict__ att0, const float* __restrict__ bias0,
    const float* __restrict__ bl1, const float* __restrict__ br1,
    const float* __restrict__ att1, const float* __restrict__ bias1,
    float* __restrict__ outEmb, float* __restrict__ outBeta)
{
    extern __shared__ uint32_t smemw[];
    uint32_t* bufHw  = smemw;                     // [32][132] fp16 words
    uint32_t* bufXRw = bufHw  + ROWS * HPW;       // [32][132] fp16 (xr)
    uint32_t* bufXLh = bufXRw + ROWS * HPW;       // [32][132] fp16 xl (logits copy)
    float*    bufXLf = (float*)(bufXLh + ROWS * HPW);  // [32][260] fp32 xl
    float*    alphaS = bufXLf + ROWS * FPW;       // [nd][i][h][j] fp32 = 1024
    float*    betaS  = alphaS + 1024;             // 128
    uint32_t* attH0  = (uint32_t*)(betaS + 128);  // [4][32] half2 words
    uint32_t* attH1  = attH0 + 128;

    const int tid = threadIdx.x;
    const int g = blockIdx.x;
    const float* xg = x + (size_t)g * (NB * RREL * EMBED);

    if (tid < 128) {
        attH0[tid] = h2(att0[2 * tid], att0[2 * tid + 1]);
        attH1[tid] = h2(att1[2 * tid], att1[2 * tid + 1]);
    }

    // Phase 1: x -> relu -> fp16 -> bufH (LDG.256 + STS.128)
#pragma unroll
    for (int i = 0; i < 4; i++) {
        int idx = tid + i * NTHREADS;             // 0..1023 float8
        uint32_t rr[8];
        ldg256(rr, xg + idx * 8);
        int f = idx * 8;
        int r = f >> 8;
        int d = f & 255;
        const float* fv = reinterpret_cast<const float*>(rr);
        uint4 p;
        p.x = h2(fmaxf(fv[0], 0.f), fmaxf(fv[1], 0.f));
        p.y = h2(fmaxf(fv[2], 0.f), fmaxf(fv[3], 0.f));
        p.z = h2(fmaxf(fv[4], 0.f), fmaxf(fv[5], 0.f));
        p.w = h2(fmaxf(fv[6], 0.f), fmaxf(fv[7], 0.f));
        *reinterpret_cast<uint4*>(bufHw + r * HPW + (d >> 1)) = p;
    }
    __syncthreads();

    // Phase 2: fused layer-0 GEMMs
    gemm_dual<false>(g_Wh + 0 * WMAT_U4, bl0, g_Wh + 1 * WMAT_U4, br0,
                     bufHw, bufXLh, bufXLf, bufXRw, tid);
    __syncthreads();

    // Phase 3: logits0 + softmax over j, half2 math, LDS.64.
    {
        int w = tid >> 5, lane = tid & 31;
        int nd = w & 3, ihalf = w >> 2;
        int j = lane >> 2, h = lane & 3;
        const uint2* at2 = reinterpret_cast<const uint2*>(attH0) + h * 16;
        const uint2* xl2 = reinterpret_cast<const uint2*>(bufXLh)
                           + (nd * 8 + j) * (HPW / 2) + h * 16;
        const uint2* xr2 = reinterpret_cast<const uint2*>(bufXRw)
                           + (nd * 8 + ihalf * 4) * (HPW / 2) + h * 16;
        const __half2 zz  = __float2half2_rn(0.f);
        const __half2 c02 = __float2half2_rn(0.2f);
        float sa[4];
#pragma unroll
        for (int ii = 0; ii < 4; ii++) sa[ii] = 0.f;
#pragma unroll 4
        for (int p = 0; p < 16; p++) {
            int cc = (p + h) & 15;                // pair-granular rotation
            uint2 xlp = xl2[cc], atp = at2[cc];
            __half2 xla = u2h(xlp.x), xlb = u2h(xlp.y);
            __half2 ata = u2h(atp.x), atb = u2h(atp.y);
#pragma unroll
            for (int ii = 0; ii < 4; ii++) {
                uint2 xrp = xr2[ii * (HPW / 2) + cc];
                __half2 v0 = __hadd2(u2h(xrp.x), xla);
                __half2 v1 = __hadd2(u2h(xrp.y), xlb);
                __half2 l0 = __hfma2(__hmin2(v0, zz), c02, __hmax2(v0, zz));
                __half2 l1 = __hfma2(__hmin2(v1, zz), c02, __hmax2(v1, zz));
                float2 p0 = __half22float2(__hmul2(ata, l0));
                float2 p1 = __half22float2(__hmul2(atb, l1));
                sa[ii] += (p0.x + p0.y) + (p1.x + p1.y);
            }
        }
#pragma unroll
        for (int ii = 0; ii < 4; ii++) {
            float s = sa[ii];
            float m = s;
            m = fmaxf(m, __shfl_xor_sync(0xffffffffu, m, 4));
            m = fmaxf(m, __shfl_xor_sync(0xffffffffu, m, 8));
            m = fmaxf(m, __shfl_xor_sync(0xffffffffu, m, 16));
            float e = __expf(s - m);
            float sum = e;
            sum += __shfl_xor_sync(0xffffffffu, sum, 4);
            sum += __shfl_xor_sync(0xffffffffu, sum, 8);
            sum += __shfl_xor_sync(0xffffffffu, sum, 16);
            alphaS[((nd * 8 + ihalf * 4 + ii) * 4 + h) * 8 + j] = e / sum;
        }
    }
    __syncthreads();

    // Phase 4: h1 = relu(alpha @ xl0 + bias0) -> bufH fp16 (fp32 inputs).
    {
        int c0 = 2 * (tid & 127);
        int ndb = (tid >> 7) * 2;
        int h = c0 >> 6;
        float b0a = bias0[c0], b0b = bias0[c0 + 1];
#pragma unroll
        for (int nn = 0; nn < 2; nn++) {
            int nd = ndb + nn;
            float xa[8], xb[8];
#pragma unroll
            for (int j = 0; j < 8; j++) {
                float2 v = *reinterpret_cast<const float2*>(
                    bufXLf + (nd * 8 + j) * FPW + c0);
                xa[j] = v.x; xb[j] = v.y;
            }
#pragma unroll
            for (int i = 0; i < 8; i++) {
                const float4* ap = reinterpret_cast<const float4*>(
                    alphaS + ((nd * 8 + i) * 4 + h) * 8);
                float4 a03 = ap[0];
                float4 a47 = ap[1];
                float al[8] = {a03.x, a03.y, a03.z, a03.w,
                               a47.x, a47.y, a47.z, a47.w};
                float sa = b0a, sb = b0b;
#pragma unroll
                for (int j = 0; j < 8; j++) {
                    sa += al[j] * xa[j];
                    sb += al[j] * xb[j];
                }
                bufHw[(nd * 8 + i) * HPW + (c0 >> 1)] =
                    h2(fmaxf(sa, 0.f), fmaxf(sb, 0.f));
            }
        }
    }
    __syncthreads();

    // Phase 5: fused layer-1 GEMMs (xl1 full; xr1 self rows)
    gemm_dual<true>(g_Wh + 2 * WMAT_U4, bl1, g_Wh + 3 * WMAT_U4, br1,
                    bufHw, bufXLh, bufXLf, bufXRw, tid);
    __syncthreads();

    // Phase 6: logits1 + softmax over r -> beta (xl fp32, xr/att fp16)
    if (tid < 128) {
        int node = tid >> 5, lane = tid & 31;
        int r = lane >> 2, h = lane & 3;
        const uint32_t* at2 = attH1 + h * 32;
        const uint32_t* xr2 = bufXRw + (node * 8 + 7) * HPW + h * 32;
        const float*    xl  = bufXLf + (node * 8 + r) * FPW + h * 64;
        float s = 0.f;
#pragma unroll 4
        for (int c2 = 0; c2 < 32; c2++) {
            int cc = (c2 + h) & 31;
            float2 xrv = __half22float2(u2h(xr2[cc]));
            float2 av  = __half22float2(u2h(at2[cc]));
            float2 xlv = *reinterpret_cast<const float2*>(xl + 2 * cc);
            s += av.x * leaky(xrv.x + xlv.x) + av.y * leaky(xrv.y + xlv.y);
        }
        float m = s;
        m = fmaxf(m, __shfl_xor_sync(0xffffffffu, m, 4));
        m = fmaxf(m, __shfl_xor_sync(0xffffffffu, m, 8));
        m = fmaxf(m, __shfl_xor_sync(0xffffffffu, m, 16));
        float e = __expf(s - m);
        float sum = e;
        sum += __shfl_xor_sync(0xffffffffu, sum, 4);
        sum += __shfl_xor_sync(0xffffffffu, sum, 8);
        sum += __shfl_xor_sync(0xffffffffu, sum, 16);
        float beta = e / sum;
        betaS[(node * 8 + r) * 4 + h] = beta;
        outBeta[(size_t)(g * NB + node) * 32 + r * 4 + h] = beta;
    }
    __syncthreads();

    // Phase 7: out = relu(beta @ xl1 + bias1), xl fp32. col = tid.
    {
        int h = tid >> 6;
        float b1 = bias1[tid];
#pragma unroll
        for (int nd = 0; nd < NB; nd++) {
            float s = b1;
#pragma unroll
            for (int r = 0; r < 8; r++)
                s += betaS[(nd * 8 + r) * 4 + h] * bufXLf[(nd * 8 + r) * FPW + tid];
            outEmb[(size_t)(g * NB + nd) * 256 + tid] = fmaxf(s, 0.f);
        }
    }
}

extern "C" void kernel_launch(void* const* d_in, const int* in_sizes, int n_in,
                              void* d_out, int out_size)
{
    const float* x     = (const float*)d_in[0];
    const float* Wl0   = (const float*)d_in[1];
    const float* bl0   = (const float*)d_in[2];
    const float* Wr0   = (const float*)d_in[3];
    const float* br0   = (const float*)d_in[4];
    const float* att0  = (const float*)d_in[5];
    const float* bias0 = (const float*)d_in[6];
    const float* Wl1   = (const float*)d_in[7];
    const float* bl1   = (const float*)d_in[8];
    const float* Wr1   = (const float*)d_in[9];
    const float* br1   = (const float*)d_in[10];
    const float* att1  = (const float*)d_in[11];
    const float* bias1 = (const float*)d_in[12];

    int nodes = in_sizes[0] / (RREL * EMBED);
    float* outEmb  = (float*)d_out;
    float* outBeta = outEmb + (size_t)nodes * EMBED;

    repack_W<<<128, 256>>>(Wl0, Wr0, Wl1, Wr1);

    size_t smem_words = 3 * ROWS * HPW + ROWS * FPW + 1024 + 128 + 256;
    size_t smem_bytes = smem_words * 4;
    cudaFuncSetAttribute(metapath_gat_kernel,
                         cudaFuncAttributeMaxDynamicSharedMemorySize,
                         (int)smem_bytes);

    metapath_gat_kernel<<<nodes / NB, NTHREADS, smem_bytes>>>(
        x, bl0, br0, att0, bias0, bl1, br1, att1, bias1, outEmb, outBeta);
}